// round 1
// baseline (speedup 1.0000x reference)
#include <cuda_runtime.h>
#include <cuda_bf16.h>
#include <math_constants.h>

// Problem shapes (fixed for this registry entry)
#define B_  256
#define T_  250
#define D_  700
#define H_  1024
#define O_  20
#define M_  (B_ * T_)   // 64000

// Scratch: d1[m][h] = input[m,:] . W1[h,:] + b1[h], m = b*T + t
__device__ float g_d1[(size_t)M_ * H_];

// ---------------------------------------------------------------------------
// Kernel 1: fp32 SGEMM  C[M,H] = A[M,D] * W1[H,D]^T + b1
// 128x128 block tile, BK=16, 256 threads, 8x8 microtile, float4 I/O.
// M=64000 and H=1024 are multiples of 128 -> no m/n guards. K tail guarded.
// ---------------------------------------------------------------------------
__global__ __launch_bounds__(256) void gemm_d1_kernel(
    const float* __restrict__ A,     // [M_, D_]
    const float* __restrict__ W,     // [H_, D_]
    const float* __restrict__ bias,  // [H_]
    float* __restrict__ C)           // [M_, H_]
{
    const int BK = 16;
    __shared__ __align__(16) float As[BK][128];
    __shared__ __align__(16) float Bs[BK][128];

    const int tid = threadIdx.x;
    const int bm = blockIdx.y * 128;
    const int bn = blockIdx.x * 128;
    const int tr = tid >> 4;    // 0..15 (m direction)
    const int tc = tid & 15;    // 0..15 (n direction)

    float acc[8][8];
#pragma unroll
    for (int i = 0; i < 8; i++)
#pragma unroll
        for (int j = 0; j < 8; j++) acc[i][j] = 0.0f;

    for (int k0 = 0; k0 < D_; k0 += BK) {
        // Load 128x16 tiles of A and W; each thread moves 2 float4 per matrix.
#pragma unroll
        for (int it = 0; it < 2; it++) {
            int q   = tid + it * 256;     // quad index 0..511
            int row = q >> 2;             // 0..127
            int col = (q & 3) * 4;        // 0,4,8,12
            int kk  = k0 + col;
            float4 av = make_float4(0.f, 0.f, 0.f, 0.f);
            float4 bv = make_float4(0.f, 0.f, 0.f, 0.f);
            if (kk + 4 <= D_) {           // D_ % 4 == 0, so quads are all-or-nothing
                av = *(const float4*)(A + (size_t)(bm + row) * D_ + kk);
                bv = *(const float4*)(W + (size_t)(bn + row) * D_ + kk);
            }
            As[col + 0][row] = av.x; As[col + 1][row] = av.y;
            As[col + 2][row] = av.z; As[col + 3][row] = av.w;
            Bs[col + 0][row] = bv.x; Bs[col + 1][row] = bv.y;
            Bs[col + 2][row] = bv.z; Bs[col + 3][row] = bv.w;
        }
        __syncthreads();

#pragma unroll
        for (int kk = 0; kk < BK; kk++) {
            float ra[8], rb[8];
            *(float4*)&ra[0] = *(const float4*)&As[kk][tr * 4];
            *(float4*)&ra[4] = *(const float4*)&As[kk][64 + tr * 4];
            *(float4*)&rb[0] = *(const float4*)&Bs[kk][tc * 4];
            *(float4*)&rb[4] = *(const float4*)&Bs[kk][64 + tc * 4];
#pragma unroll
            for (int i = 0; i < 8; i++)
#pragma unroll
                for (int j = 0; j < 8; j++)
                    acc[i][j] += ra[i] * rb[j];
        }
        __syncthreads();
    }

    // Epilogue: add bias, store float4
#pragma unroll
    for (int i = 0; i < 8; i++) {
        int m = bm + ((i < 4) ? (tr * 4 + i) : (64 + tr * 4 + (i - 4)));
#pragma unroll
        for (int jq = 0; jq < 2; jq++) {
            int n = bn + ((jq == 0) ? (tc * 4) : (64 + tc * 4));
            float4 v;
            v.x = acc[i][jq * 4 + 0] + bias[n + 0];
            v.y = acc[i][jq * 4 + 1] + bias[n + 1];
            v.z = acc[i][jq * 4 + 2] + bias[n + 2];
            v.w = acc[i][jq * 4 + 3] + bias[n + 3];
            *(float4*)(C + (size_t)m * H_ + n) = v;
        }
    }
}

// ---------------------------------------------------------------------------
// Kernel 2: recurrence. One CTA per batch sample (256 CTAs x 256 threads).
// Thread owns 4 hidden units (h = tid + j*256): mem1/spk in registers,
// W2 columns for those h in registers (80 regs). d2 via shuffle tree +
// cross-warp smem reduce; softmax/EMA/accumulate in warp 0 lanes 0..19.
// ---------------------------------------------------------------------------
__global__ __launch_bounds__(256) void recur_kernel(
    const float* __restrict__ d1,    // [B_*T_, H_] with row b*T_+t
    const float* __restrict__ tau1,  // [H_]
    const float* __restrict__ W2,    // [O_, H_]
    const float* __restrict__ b2,    // [O_]
    const float* __restrict__ tau2,  // [O_]
    float* __restrict__ out)         // [B_, O_]
{
    const int b    = blockIdx.x;
    const int tid  = threadIdx.x;
    const int lane = tid & 31;
    const int warp = tid >> 5;

    __shared__ float red[8][O_];

    float a1[4], om1[4], mem1[4], spk[4];
    float w2r[4][O_];
#pragma unroll
    for (int j = 0; j < 4; j++) {
        int h = tid + j * 256;
        float t = tau1[h];
        a1[j]  = 1.0f / (1.0f + expf(-t));
        om1[j] = 1.0f - a1[j];
        mem1[j] = 0.0f; spk[j] = 0.0f;
#pragma unroll
        for (int o = 0; o < O_; o++) w2r[j][o] = W2[o * H_ + h];
    }

    // warp-0 readout state
    float a2 = 0.0f, bb2 = 0.0f, mem2 = 0.0f, accv = 0.0f;
    if (warp == 0 && lane < O_) {
        a2  = 1.0f / (1.0f + expf(-tau2[lane]));
        bb2 = b2[lane];
    }

    const float* dp = d1 + (size_t)b * T_ * H_;
    float nxt[4];
#pragma unroll
    for (int j = 0; j < 4; j++) nxt[j] = dp[tid + j * 256];

    for (int t = 0; t < T_; t++) {
        float cur[4];
#pragma unroll
        for (int j = 0; j < 4; j++) cur[j] = nxt[j];
        if (t + 1 < T_) {
            const float* dn = dp + (size_t)(t + 1) * H_;
#pragma unroll
            for (int j = 0; j < 4; j++) nxt[j] = dn[tid + j * 256];
        }

        float part[O_];
#pragma unroll
        for (int o = 0; o < O_; o++) part[o] = 0.0f;

#pragma unroll
        for (int j = 0; j < 4; j++) {
            mem1[j] = mem1[j] * a1[j] + om1[j] * cur[j] - spk[j];
            spk[j]  = (mem1[j] > 1.0f) ? 1.0f : 0.0f;
#pragma unroll
            for (int o = 0; o < O_; o++) part[o] += spk[j] * w2r[j][o];
        }

        // intra-warp reduce (all 20 partials)
#pragma unroll
        for (int off = 16; off > 0; off >>= 1) {
#pragma unroll
            for (int o = 0; o < O_; o++)
                part[o] += __shfl_down_sync(0xffffffffu, part[o], off);
        }
        if (lane == 0) {
#pragma unroll
            for (int o = 0; o < O_; o++) red[warp][o] = part[o];
        }
        __syncthreads();

        if (warp == 0) {
            float d2 = bb2;
            if (lane < O_) {
#pragma unroll
                for (int w = 0; w < 8; w++) d2 += red[w][lane];
            }
            mem2 = mem2 * a2 + (1.0f - a2) * d2;  // lanes>=20: stays 0
            float v = (lane < O_) ? mem2 : -CUDART_INF_F;
            float mx = v;
#pragma unroll
            for (int off = 16; off > 0; off >>= 1)
                mx = fmaxf(mx, __shfl_xor_sync(0xffffffffu, mx, off));
            float e = (lane < O_) ? expf(mem2 - mx) : 0.0f;
            float s = e;
#pragma unroll
            for (int off = 16; off > 0; off >>= 1)
                s += __shfl_xor_sync(0xffffffffu, s, off);
            if (t > 10 && lane < O_) accv += e / s;
        }
        __syncthreads();  // protect red[] before next iteration's writes
    }

    if (warp == 0 && lane < O_) out[b * O_ + lane] = accv;
}

// ---------------------------------------------------------------------------
extern "C" void kernel_launch(void* const* d_in, const int* in_sizes, int n_in,
                              void* d_out, int out_size)
{
    const float* input = (const float*)d_in[0];  // [B,T,D]
    const float* W1    = (const float*)d_in[1];  // [H,D]
    const float* b1    = (const float*)d_in[2];  // [H]
    const float* tau1  = (const float*)d_in[3];  // [H]
    const float* W2    = (const float*)d_in[4];  // [O,H]
    const float* b2    = (const float*)d_in[5];  // [O]
    const float* tau2  = (const float*)d_in[6];  // [O]
    float* out = (float*)d_out;                  // [B,O]

    dim3 ggrid(H_ / 128, M_ / 128);              // (8, 500)
    gemm_d1_kernel<<<ggrid, 256>>>(input, W1, b1, g_d1);
    recur_kernel<<<B_, 256>>>(g_d1, tau1, W2, b2, tau2, out);
}

// round 3
// speedup vs baseline: 2.1887x; 2.1887x over previous
#include <cuda_runtime.h>
#include <cuda_bf16.h>
#include <math_constants.h>
#include <cstdint>

// ---------------- shapes ----------------
#define B_  256
#define T_  250
#define D_  700
#define H_  1024
#define O_  20
#define M_  (B_ * T_)   // 64000
#define KP_ 704         // K padded to multiple of 64

// ---------------- GEMM tiling ----------------
#define BM 128
#define BN 128
#define BK 64
#define NCHUNK (KP_ / BK)              // 11
#define TILE_B (128 * BK * 2)          // 16384 bytes per operand tile
#define STAGE_B (6 * TILE_B)           // 98304 bytes (3 A-splits + 3 W-splits)
#define SMEM_TOTAL (2 * STAGE_B)       // 196608

// ---------------- scratch (static device globals; no allocation) ----------------
__device__ float g_d1[(size_t)M_ * H_];
__device__ __nv_bfloat16 g_A0[(size_t)M_ * KP_];
__device__ __nv_bfloat16 g_A1[(size_t)M_ * KP_];
__device__ __nv_bfloat16 g_A2[(size_t)M_ * KP_];
__device__ __nv_bfloat16 g_B0[(size_t)H_ * KP_];
__device__ __nv_bfloat16 g_B1[(size_t)H_ * KP_];
__device__ __nv_bfloat16 g_B2[(size_t)H_ * KP_];

// ---------------- family-safe PTX helpers ----------------
__device__ __forceinline__ uint32_t smem_to_u32(const void* smem_ptr) {
    uint32_t addr;
    asm("{ .reg .u64 tmp; cvta.to.shared.u64 tmp, %1; cvt.u32.u64 %0, tmp; }"
        : "=r"(addr) : "l"(smem_ptr));
    return addr;
}
#define CP_ASYNC16(dst_u32, src_ptr) \
    asm volatile("cp.async.cg.shared.global [%0], [%1], 16;" \
        :: "r"(dst_u32), "l"(src_ptr))
#define CP_COMMIT() asm volatile("cp.async.commit_group;" ::: "memory")
#define CP_WAIT1()  asm volatile("cp.async.wait_group 1;" ::: "memory")

__device__ __forceinline__ void ldsm_x4(uint32_t& r0, uint32_t& r1,
                                        uint32_t& r2, uint32_t& r3, uint32_t addr) {
    asm volatile("ldmatrix.sync.aligned.m8n8.x4.shared.b16 {%0,%1,%2,%3}, [%4];"
        : "=r"(r0), "=r"(r1), "=r"(r2), "=r"(r3) : "r"(addr));
}
__device__ __forceinline__ void mma16816(float* c, const uint32_t* a, const uint32_t* b) {
    asm volatile(
        "mma.sync.aligned.m16n8k16.row.col.f32.bf16.bf16.f32 "
        "{%0,%1,%2,%3}, {%4,%5,%6,%7}, {%8,%9}, {%0,%1,%2,%3};"
        : "+f"(c[0]), "+f"(c[1]), "+f"(c[2]), "+f"(c[3])
        : "r"(a[0]), "r"(a[1]), "r"(a[2]), "r"(a[3]), "r"(b[0]), "r"(b[1]));
}
#define SWZ128(o) ((o) ^ (((o) >> 3) & 0x70))

// ---------------------------------------------------------------------------
// Kernel 0: fp32 -> 3x bf16 split (hi/mid/lo), K padded 700 -> 704 with zeros.
// ---------------------------------------------------------------------------
__global__ void split_kernel(const float* __restrict__ src, int rows,
                             __nv_bfloat16* __restrict__ o0,
                             __nv_bfloat16* __restrict__ o1,
                             __nv_bfloat16* __restrict__ o2)
{
    const int GPR = KP_ / 4;  // 176 groups per row
    long long idx = (long long)blockIdx.x * blockDim.x + threadIdx.x;
    if (idx >= (long long)rows * GPR) return;
    int m  = (int)(idx / GPR);
    int kg = (int)(idx % GPR);
    float a[4] = {0.f, 0.f, 0.f, 0.f};
    if (kg * 4 < D_) {
        float4 v = *(const float4*)(src + (size_t)m * D_ + kg * 4);
        a[0] = v.x; a[1] = v.y; a[2] = v.z; a[3] = v.w;
    }
    unsigned short h0[4], h1[4], h2[4];
#pragma unroll
    for (int i = 0; i < 4; i++) {
        __nv_bfloat16 b0 = __float2bfloat16(a[i]);
        float r = a[i] - __bfloat162float(b0);
        __nv_bfloat16 b1 = __float2bfloat16(r);
        r -= __bfloat162float(b1);
        __nv_bfloat16 b2 = __float2bfloat16(r);
        h0[i] = __bfloat16_as_ushort(b0);
        h1[i] = __bfloat16_as_ushort(b1);
        h2[i] = __bfloat16_as_ushort(b2);
    }
    size_t off = (size_t)m * KP_ + kg * 4;
    *(uint2*)(o0 + off) = make_uint2((uint32_t)h0[1] << 16 | h0[0], (uint32_t)h0[3] << 16 | h0[2]);
    *(uint2*)(o1 + off) = make_uint2((uint32_t)h1[1] << 16 | h1[0], (uint32_t)h1[3] << 16 | h1[2]);
    *(uint2*)(o2 + off) = make_uint2((uint32_t)h2[1] << 16 | h2[0], (uint32_t)h2[3] << 16 | h2[2]);
}

// ---------------------------------------------------------------------------
// Kernel 1: HMMA (mma.sync bf16) GEMM with fp32 emulation (6 cross-products).
// C[M,H] = A[M,K] * W[H,K]^T + bias. BM=BN=128, BK=64, 2-stage cp.async.
// 8 warps (2 m x 4 n), warp tile 64x32, m16n8k16.
// ---------------------------------------------------------------------------
__global__ __launch_bounds__(256)
void gemm_hmma_kernel(const float* __restrict__ bias)
{
    extern __shared__ __align__(1024) char smem[];
    const uint32_t smem_base = smem_to_u32(smem);
    const int tid  = threadIdx.x;
    const int wid  = tid >> 5;
    const int lane = tid & 31;
    const int wm = wid >> 2;       // 0..1  (m)
    const int wn = wid & 3;        // 0..3  (n)
    const int bm = blockIdx.y * BM;
    const int bn = blockIdx.x * BN;

    // ---- cp.async geometry: per tile, thread handles 4 chunks of 16B ----
    // chunk c: row = c>>3 (0..127), col16 = c&7
    uint32_t sdst[4];
    size_t   goff[4];
#pragma unroll
    for (int j = 0; j < 4; j++) {
        int c = tid + j * 256;
        int row = c >> 3, col = c & 7;
        sdst[j] = SWZ128(row * 128 + col * 16);
        goff[j] = (size_t)row * KP_ + col * 8;
    }
    const __nv_bfloat16* gsrc[6];
    gsrc[0] = g_A0 + (size_t)bm * KP_;
    gsrc[1] = g_A1 + (size_t)bm * KP_;
    gsrc[2] = g_A2 + (size_t)bm * KP_;
    gsrc[3] = g_B0 + (size_t)bn * KP_;
    gsrc[4] = g_B1 + (size_t)bn * KP_;
    gsrc[5] = g_B2 + (size_t)bn * KP_;

    // ---- ldmatrix per-lane address pieces ----
    const int q  = lane >> 3;      // 0..3 quadrant
    const int rr = lane & 7;
    // A: mt in 0..3 -> 16x16 frag at (wm*64 + mt*16, kk*16)
    uint32_t abyte[4];
#pragma unroll
    for (int mt = 0; mt < 4; mt++) {
        int row = wm * 64 + mt * 16 + (q & 1) * 8 + rr;
        abyte[mt] = (uint32_t)(row * 128 + (q >> 1) * 16);
    }
    // B: np in 0..1 -> two n8k16 frags at (wn*32 + np*16 .. +16, kk*16)
    uint32_t bbyte[2];
#pragma unroll
    for (int np = 0; np < 2; np++) {
        int row = wn * 32 + np * 16 + (q >> 1) * 8 + rr;
        bbyte[np] = (uint32_t)(row * 128 + (q & 1) * 16);
    }

    float acc[4][4][4];
#pragma unroll
    for (int mt = 0; mt < 4; mt++)
#pragma unroll
        for (int nt = 0; nt < 4; nt++)
#pragma unroll
            for (int i = 0; i < 4; i++) acc[mt][nt][i] = 0.0f;

    // ---- prologue: load chunks 0 and 1 ----
#pragma unroll
    for (int pk = 0; pk < 2; pk++) {
        uint32_t sb = smem_base + pk * STAGE_B;
#pragma unroll
        for (int tix = 0; tix < 6; tix++)
#pragma unroll
            for (int j = 0; j < 4; j++)
                CP_ASYNC16(sb + tix * TILE_B + sdst[j], gsrc[tix] + goff[j] + pk * BK);
        CP_COMMIT();
    }

    const int pa[6] = {0, 0, 1, 1, 0, 2};
    const int pb[6] = {0, 1, 0, 1, 2, 0};

    for (int k = 0; k < NCHUNK; k++) {
        CP_WAIT1();            // chunk k resident (k+1 may still be in flight)
        __syncthreads();

        const uint32_t stage = smem_base + (k & 1) * STAGE_B;
#pragma unroll
        for (int kk = 0; kk < 4; kk++) {
            uint32_t af[3][4][4];
            uint32_t bf[3][4][2];
#pragma unroll
            for (int s = 0; s < 3; s++) {
                uint32_t ab = stage + s * TILE_B;
                uint32_t bb = stage + (3 + s) * TILE_B;
#pragma unroll
                for (int mt = 0; mt < 4; mt++) {
                    uint32_t byte = abyte[mt] + kk * 32;
                    ldsm_x4(af[s][mt][0], af[s][mt][1], af[s][mt][2], af[s][mt][3],
                            ab + SWZ128(byte));
                }
#pragma unroll
                for (int np = 0; np < 2; np++) {
                    uint32_t byte = bbyte[np] + kk * 32;
                    ldsm_x4(bf[s][np * 2][0], bf[s][np * 2][1],
                            bf[s][np * 2 + 1][0], bf[s][np * 2 + 1][1],
                            bb + SWZ128(byte));
                }
            }
#pragma unroll
            for (int p = 0; p < 6; p++)
#pragma unroll
                for (int mt = 0; mt < 4; mt++)
#pragma unroll
                    for (int nt = 0; nt < 4; nt++)
                        mma16816(acc[mt][nt], af[pa[p]][mt], bf[pb[p]][nt]);
        }
        __syncthreads();

        // issue loads for chunk k+2 into the buffer just freed
        if (k + 2 < NCHUNK) {
            uint32_t sb = smem_base + (k & 1) * STAGE_B;
            int k0 = (k + 2) * BK;
#pragma unroll
            for (int tix = 0; tix < 6; tix++)
#pragma unroll
                for (int j = 0; j < 4; j++)
                    CP_ASYNC16(sb + tix * TILE_B + sdst[j], gsrc[tix] + goff[j] + k0);
        }
        CP_COMMIT();           // always commit to keep group accounting aligned
    }

    // ---- epilogue: add bias, write fp32 ----
    const int mrow0 = bm + wm * 64;
    const int ncol0 = bn + wn * 32;
    const int lr = lane >> 2;
    const int lc = (lane & 3) * 2;
#pragma unroll
    for (int mt = 0; mt < 4; mt++) {
#pragma unroll
        for (int nt = 0; nt < 4; nt++) {
            int r = mrow0 + mt * 16 + lr;
            int c = ncol0 + nt * 8 + lc;
            float bx = __ldg(bias + c), by = __ldg(bias + c + 1);
            float2 v0 = make_float2(acc[mt][nt][0] + bx, acc[mt][nt][1] + by);
            float2 v1 = make_float2(acc[mt][nt][2] + bx, acc[mt][nt][3] + by);
            *(float2*)(g_d1 + (size_t)r * H_ + c)       = v0;
            *(float2*)(g_d1 + (size_t)(r + 8) * H_ + c) = v1;
        }
    }
}

// ---------------------------------------------------------------------------
// Kernel 2: recurrence (unchanged; ~noise vs GEMM).
// ---------------------------------------------------------------------------
__global__ __launch_bounds__(256) void recur_kernel(
    const float* __restrict__ d1,
    const float* __restrict__ tau1,
    const float* __restrict__ W2,
    const float* __restrict__ b2,
    const float* __restrict__ tau2,
    float* __restrict__ out)
{
    const int b    = blockIdx.x;
    const int tid  = threadIdx.x;
    const int lane = tid & 31;
    const int warp = tid >> 5;

    __shared__ float red[8][O_];

    float a1[4], om1[4], mem1[4], spk[4];
    float w2r[4][O_];
#pragma unroll
    for (int j = 0; j < 4; j++) {
        int h = tid + j * 256;
        float t = tau1[h];
        a1[j]  = 1.0f / (1.0f + expf(-t));
        om1[j] = 1.0f - a1[j];
        mem1[j] = 0.0f; spk[j] = 0.0f;
#pragma unroll
        for (int o = 0; o < O_; o++) w2r[j][o] = W2[o * H_ + h];
    }

    float a2 = 0.0f, bb2 = 0.0f, mem2 = 0.0f, accv = 0.0f;
    if (warp == 0 && lane < O_) {
        a2  = 1.0f / (1.0f + expf(-tau2[lane]));
        bb2 = b2[lane];
    }

    const float* dp = d1 + (size_t)b * T_ * H_;
    float nxt[4];
#pragma unroll
    for (int j = 0; j < 4; j++) nxt[j] = dp[tid + j * 256];

    for (int t = 0; t < T_; t++) {
        float cur[4];
#pragma unroll
        for (int j = 0; j < 4; j++) cur[j] = nxt[j];
        if (t + 1 < T_) {
            const float* dn = dp + (size_t)(t + 1) * H_;
#pragma unroll
            for (int j = 0; j < 4; j++) nxt[j] = dn[tid + j * 256];
        }

        float part[O_];
#pragma unroll
        for (int o = 0; o < O_; o++) part[o] = 0.0f;

#pragma unroll
        for (int j = 0; j < 4; j++) {
            mem1[j] = mem1[j] * a1[j] + om1[j] * cur[j] - spk[j];
            spk[j]  = (mem1[j] > 1.0f) ? 1.0f : 0.0f;
#pragma unroll
            for (int o = 0; o < O_; o++) part[o] += spk[j] * w2r[j][o];
        }

#pragma unroll
        for (int off = 16; off > 0; off >>= 1) {
#pragma unroll
            for (int o = 0; o < O_; o++)
                part[o] += __shfl_down_sync(0xffffffffu, part[o], off);
        }
        if (lane == 0) {
#pragma unroll
            for (int o = 0; o < O_; o++) red[warp][o] = part[o];
        }
        __syncthreads();

        if (warp == 0) {
            float d2 = bb2;
            if (lane < O_) {
#pragma unroll
                for (int w = 0; w < 8; w++) d2 += red[w][lane];
            }
            mem2 = mem2 * a2 + (1.0f - a2) * d2;
            float v = (lane < O_) ? mem2 : -CUDART_INF_F;
            float mx = v;
#pragma unroll
            for (int off = 16; off > 0; off >>= 1)
                mx = fmaxf(mx, __shfl_xor_sync(0xffffffffu, mx, off));
            float e = (lane < O_) ? expf(mem2 - mx) : 0.0f;
            float s = e;
#pragma unroll
            for (int off = 16; off > 0; off >>= 1)
                s += __shfl_xor_sync(0xffffffffu, s, off);
            if (t > 10 && lane < O_) accv += e / s;
        }
        __syncthreads();
    }

    if (warp == 0 && lane < O_) out[b * O_ + lane] = accv;
}

// ---------------------------------------------------------------------------
extern "C" void kernel_launch(void* const* d_in, const int* in_sizes, int n_in,
                              void* d_out, int out_size)
{
    const float* input = (const float*)d_in[0];  // [B,T,D]
    const float* W1    = (const float*)d_in[1];  // [H,D]
    const float* b1    = (const float*)d_in[2];  // [H]
    const float* tau1  = (const float*)d_in[3];  // [H]
    const float* W2    = (const float*)d_in[4];  // [O,H]
    const float* b2    = (const float*)d_in[5];  // [O]
    const float* tau2  = (const float*)d_in[6];  // [O]
    float* out = (float*)d_out;                  // [B,O]

    cudaFuncSetAttribute(gemm_hmma_kernel,
                         cudaFuncAttributeMaxDynamicSharedMemorySize, SMEM_TOTAL);

    __nv_bfloat16 *a0, *a1, *a2, *w0, *w1s, *w2s;
    cudaGetSymbolAddress((void**)&a0,  g_A0);
    cudaGetSymbolAddress((void**)&a1,  g_A1);
    cudaGetSymbolAddress((void**)&a2,  g_A2);
    cudaGetSymbolAddress((void**)&w0,  g_B0);
    cudaGetSymbolAddress((void**)&w1s, g_B1);
    cudaGetSymbolAddress((void**)&w2s, g_B2);

    {
        long long ng = (long long)M_ * (KP_ / 4);
        int blocks = (int)((ng + 255) / 256);
        split_kernel<<<blocks, 256>>>(input, M_, a0, a1, a2);
    }
    {
        long long ng = (long long)H_ * (KP_ / 4);
        int blocks = (int)((ng + 255) / 256);
        split_kernel<<<blocks, 256>>>(W1, H_, w0, w1s, w2s);
    }

    dim3 ggrid(H_ / BN, M_ / BM);  // (8, 500)
    gemm_hmma_kernel<<<ggrid, 256, SMEM_TOTAL>>>(b1);

    float* d1p;
    cudaGetSymbolAddress((void**)&d1p, g_d1);
    recur_kernel<<<B_, 256>>>(d1p, tau1, W2, b2, tau2, out);
}

// round 4
// speedup vs baseline: 2.3169x; 1.0586x over previous
#include <cuda_runtime.h>
#include <cuda_bf16.h>
#include <math_constants.h>
#include <cstdint>

// ---------------- shapes ----------------
#define B_  256
#define T_  250
#define D_  700
#define H_  1024
#define O_  20
#define M_  (B_ * T_)   // 64000
#define KP_ 704         // K padded to multiple of 64

// ---------------- main GEMM tiling ----------------
#define BM 128
#define BN 128
#define BK 64
#define NCHUNK (KP_ / BK)              // 11
#define TILE_B (128 * BK * 2)          // 16384 bytes per operand tile
#define STAGE_B (6 * TILE_B)           // 98304 bytes (3 A-splits + 3 W-splits)
#define SMEM_TOTAL (2 * STAGE_B)       // 196608

// ---------------- phase-B (d2) GEMM tiling ----------------
#define PB_ROWS 512                    // spike rows per CTA
#define PB_K    1024
#define PB_BK   64
#define PB_NCH  (PB_K / PB_BK)         // 16
#define PB_SPK_B (PB_ROWS * PB_BK * 2) // 65536
#define PB_W2_B  (32 * PB_BK * 2)      // 4096 per split
#define PB_STAGE (PB_SPK_B + 2 * PB_W2_B)   // 73728
#define PB_SMEM  (2 * PB_STAGE)        // 147456

// ---------------- scratch (static device globals; no allocation) ----------------
__device__ float g_d1[(size_t)M_ * H_];
__device__ __nv_bfloat16 g_A0[(size_t)M_ * KP_];
__device__ __nv_bfloat16 g_A1[(size_t)M_ * KP_];
__device__ __nv_bfloat16 g_A2[(size_t)M_ * KP_];
__device__ __nv_bfloat16 g_B0[(size_t)H_ * KP_];
__device__ __nv_bfloat16 g_B1[(size_t)H_ * KP_];
__device__ __nv_bfloat16 g_B2[(size_t)H_ * KP_];
__device__ __nv_bfloat16 g_spk[(size_t)M_ * H_];      // bf16 spikes (0/1)
__device__ __nv_bfloat16 g_W2s[2][32 * PB_K];          // W2 hi/lo splits, padded to 32 rows
__device__ float g_d2[(size_t)M_ * 32];                // d2 (padded to 32 outputs)

// ---------------- family-safe PTX helpers ----------------
__device__ __forceinline__ uint32_t smem_to_u32(const void* smem_ptr) {
    uint32_t addr;
    asm("{ .reg .u64 tmp; cvta.to.shared.u64 tmp, %1; cvt.u32.u64 %0, tmp; }"
        : "=r"(addr) : "l"(smem_ptr));
    return addr;
}
#define CP_ASYNC16(dst_u32, src_ptr) \
    asm volatile("cp.async.cg.shared.global [%0], [%1], 16;" \
        :: "r"(dst_u32), "l"(src_ptr))
#define CP_COMMIT() asm volatile("cp.async.commit_group;" ::: "memory")
#define CP_WAIT1()  asm volatile("cp.async.wait_group 1;" ::: "memory")

__device__ __forceinline__ void ldsm_x4(uint32_t& r0, uint32_t& r1,
                                        uint32_t& r2, uint32_t& r3, uint32_t addr) {
    asm volatile("ldmatrix.sync.aligned.m8n8.x4.shared.b16 {%0,%1,%2,%3}, [%4];"
        : "=r"(r0), "=r"(r1), "=r"(r2), "=r"(r3) : "r"(addr));
}
__device__ __forceinline__ void mma16816(float* c, const uint32_t* a, const uint32_t* b) {
    asm volatile(
        "mma.sync.aligned.m16n8k16.row.col.f32.bf16.bf16.f32 "
        "{%0,%1,%2,%3}, {%4,%5,%6,%7}, {%8,%9}, {%0,%1,%2,%3};"
        : "+f"(c[0]), "+f"(c[1]), "+f"(c[2]), "+f"(c[3])
        : "r"(a[0]), "r"(a[1]), "r"(a[2]), "r"(a[3]), "r"(b[0]), "r"(b[1]));
}
#define SWZ128(o) ((o) ^ (((o) >> 3) & 0x70))

// ---------------------------------------------------------------------------
// Kernel 0: fp32 -> 3x bf16 split (hi/mid/lo), K padded 700 -> 704 with zeros.
// ---------------------------------------------------------------------------
__global__ void split_kernel(const float* __restrict__ src, int rows,
                             __nv_bfloat16* __restrict__ o0,
                             __nv_bfloat16* __restrict__ o1,
                             __nv_bfloat16* __restrict__ o2)
{
    const int GPR = KP_ / 4;  // 176 groups per row
    long long idx = (long long)blockIdx.x * blockDim.x + threadIdx.x;
    if (idx >= (long long)rows * GPR) return;
    int m  = (int)(idx / GPR);
    int kg = (int)(idx % GPR);
    float a[4] = {0.f, 0.f, 0.f, 0.f};
    if (kg * 4 < D_) {
        float4 v = *(const float4*)(src + (size_t)m * D_ + kg * 4);
        a[0] = v.x; a[1] = v.y; a[2] = v.z; a[3] = v.w;
    }
    unsigned short h0[4], h1[4], h2[4];
#pragma unroll
    for (int i = 0; i < 4; i++) {
        __nv_bfloat16 b0 = __float2bfloat16(a[i]);
        float r = a[i] - __bfloat162float(b0);
        __nv_bfloat16 b1 = __float2bfloat16(r);
        r -= __bfloat162float(b1);
        __nv_bfloat16 b2 = __float2bfloat16(r);
        h0[i] = __bfloat16_as_ushort(b0);
        h1[i] = __bfloat16_as_ushort(b1);
        h2[i] = __bfloat16_as_ushort(b2);
    }
    size_t off = (size_t)m * KP_ + kg * 4;
    *(uint2*)(o0 + off) = make_uint2((uint32_t)h0[1] << 16 | h0[0], (uint32_t)h0[3] << 16 | h0[2]);
    *(uint2*)(o1 + off) = make_uint2((uint32_t)h1[1] << 16 | h1[0], (uint32_t)h1[3] << 16 | h1[2]);
    *(uint2*)(o2 + off) = make_uint2((uint32_t)h2[1] << 16 | h2[0], (uint32_t)h2[3] << 16 | h2[2]);
}

// ---------------------------------------------------------------------------
// Kernel 0b: W2 [20,1024] fp32 -> 2x bf16 splits padded to [32,1024].
// ---------------------------------------------------------------------------
__global__ void split_w2_kernel(const float* __restrict__ W2)
{
    int idx = blockIdx.x * blockDim.x + threadIdx.x;   // 0 .. 32*1024-1
    if (idx >= 32 * PB_K) return;
    int row = idx / PB_K;
    float v = (row < O_) ? W2[row * H_ + (idx % PB_K)] : 0.0f;
    __nv_bfloat16 hi = __float2bfloat16(v);
    __nv_bfloat16 lo = __float2bfloat16(v - __bfloat162float(hi));
    g_W2s[0][idx] = hi;
    g_W2s[1][idx] = lo;
}

// ---------------------------------------------------------------------------
// Kernel 1: HMMA GEMM with fp32 emulation (6 cross-products). Unchanged R3.
// ---------------------------------------------------------------------------
__global__ __launch_bounds__(256)
void gemm_hmma_kernel(const float* __restrict__ bias)
{
    extern __shared__ __align__(1024) char smem[];
    const uint32_t smem_base = smem_to_u32(smem);
    const int tid  = threadIdx.x;
    const int wid  = tid >> 5;
    const int lane = tid & 31;
    const int wm = wid >> 2;
    const int wn = wid & 3;
    const int bm = blockIdx.y * BM;
    const int bn = blockIdx.x * BN;

    uint32_t sdst[4];
    size_t   goff[4];
#pragma unroll
    for (int j = 0; j < 4; j++) {
        int c = tid + j * 256;
        int row = c >> 3, col = c & 7;
        sdst[j] = SWZ128(row * 128 + col * 16);
        goff[j] = (size_t)row * KP_ + col * 8;
    }
    const __nv_bfloat16* gsrc[6];
    gsrc[0] = g_A0 + (size_t)bm * KP_;
    gsrc[1] = g_A1 + (size_t)bm * KP_;
    gsrc[2] = g_A2 + (size_t)bm * KP_;
    gsrc[3] = g_B0 + (size_t)bn * KP_;
    gsrc[4] = g_B1 + (size_t)bn * KP_;
    gsrc[5] = g_B2 + (size_t)bn * KP_;

    const int q  = lane >> 3;
    const int rr = lane & 7;
    uint32_t abyte[4];
#pragma unroll
    for (int mt = 0; mt < 4; mt++) {
        int row = wm * 64 + mt * 16 + (q & 1) * 8 + rr;
        abyte[mt] = (uint32_t)(row * 128 + (q >> 1) * 16);
    }
    uint32_t bbyte[2];
#pragma unroll
    for (int np = 0; np < 2; np++) {
        int row = wn * 32 + np * 16 + (q >> 1) * 8 + rr;
        bbyte[np] = (uint32_t)(row * 128 + (q & 1) * 16);
    }

    float acc[4][4][4];
#pragma unroll
    for (int mt = 0; mt < 4; mt++)
#pragma unroll
        for (int nt = 0; nt < 4; nt++)
#pragma unroll
            for (int i = 0; i < 4; i++) acc[mt][nt][i] = 0.0f;

#pragma unroll
    for (int pk = 0; pk < 2; pk++) {
        uint32_t sb = smem_base + pk * STAGE_B;
#pragma unroll
        for (int tix = 0; tix < 6; tix++)
#pragma unroll
            for (int j = 0; j < 4; j++)
                CP_ASYNC16(sb + tix * TILE_B + sdst[j], gsrc[tix] + goff[j] + pk * BK);
        CP_COMMIT();
    }

    const int pa[6] = {0, 0, 1, 1, 0, 2};
    const int pb[6] = {0, 1, 0, 1, 2, 0};

    for (int k = 0; k < NCHUNK; k++) {
        CP_WAIT1();
        __syncthreads();

        const uint32_t stage = smem_base + (k & 1) * STAGE_B;
#pragma unroll
        for (int kk = 0; kk < 4; kk++) {
            uint32_t af[3][4][4];
            uint32_t bf[3][4][2];
#pragma unroll
            for (int s = 0; s < 3; s++) {
                uint32_t ab = stage + s * TILE_B;
                uint32_t bb = stage + (3 + s) * TILE_B;
#pragma unroll
                for (int mt = 0; mt < 4; mt++) {
                    uint32_t byte = abyte[mt] + kk * 32;
                    ldsm_x4(af[s][mt][0], af[s][mt][1], af[s][mt][2], af[s][mt][3],
                            ab + SWZ128(byte));
                }
#pragma unroll
                for (int np = 0; np < 2; np++) {
                    uint32_t byte = bbyte[np] + kk * 32;
                    ldsm_x4(bf[s][np * 2][0], bf[s][np * 2][1],
                            bf[s][np * 2 + 1][0], bf[s][np * 2 + 1][1],
                            bb + SWZ128(byte));
                }
            }
#pragma unroll
            for (int p = 0; p < 6; p++)
#pragma unroll
                for (int mt = 0; mt < 4; mt++)
#pragma unroll
                    for (int nt = 0; nt < 4; nt++)
                        mma16816(acc[mt][nt], af[pa[p]][mt], bf[pb[p]][nt]);
        }
        __syncthreads();

        if (k + 2 < NCHUNK) {
            uint32_t sb = smem_base + (k & 1) * STAGE_B;
            int k0 = (k + 2) * BK;
#pragma unroll
            for (int tix = 0; tix < 6; tix++)
#pragma unroll
                for (int j = 0; j < 4; j++)
                    CP_ASYNC16(sb + tix * TILE_B + sdst[j], gsrc[tix] + goff[j] + k0);
        }
        CP_COMMIT();
    }

    const int mrow0 = bm + wm * 64;
    const int ncol0 = bn + wn * 32;
    const int lr = lane >> 2;
    const int lc = (lane & 3) * 2;
#pragma unroll
    for (int mt = 0; mt < 4; mt++) {
#pragma unroll
        for (int nt = 0; nt < 4; nt++) {
            int r = mrow0 + mt * 16 + lr;
            int c = ncol0 + nt * 8 + lc;
            float bx = __ldg(bias + c), by = __ldg(bias + c + 1);
            float2 v0 = make_float2(acc[mt][nt][0] + bx, acc[mt][nt][1] + by);
            float2 v1 = make_float2(acc[mt][nt][2] + bx, acc[mt][nt][3] + by);
            *(float2*)(g_d1 + (size_t)r * H_ + c)       = v0;
            *(float2*)(g_d1 + (size_t)(r + 8) * H_ + c) = v1;
        }
    }
}

// ---------------------------------------------------------------------------
// Kernel 2a (phase A): LIF layer-1 chains. CTA per batch sample, thread owns
// 4 consecutive h. Streams d1, writes bf16 spikes. DRAM-bound.
// ---------------------------------------------------------------------------
__global__ __launch_bounds__(256) void lif1_kernel(
    const float* __restrict__ d1,
    const float* __restrict__ tau1,
    __nv_bfloat16* __restrict__ spk_out)
{
    const int b   = blockIdx.x;
    const int tid = threadIdx.x;

    float4 tv = *(const float4*)(tau1 + tid * 4);
    float a1[4], om[4], mem[4], spk[4];
    a1[0] = 1.0f / (1.0f + expf(-tv.x));
    a1[1] = 1.0f / (1.0f + expf(-tv.y));
    a1[2] = 1.0f / (1.0f + expf(-tv.z));
    a1[3] = 1.0f / (1.0f + expf(-tv.w));
#pragma unroll
    for (int j = 0; j < 4; j++) { om[j] = 1.0f - a1[j]; mem[j] = 0.0f; spk[j] = 0.0f; }

    const float* dp = d1 + (size_t)b * T_ * H_ + tid * 4;
    __nv_bfloat16* sp = spk_out + (size_t)b * T_ * H_ + tid * 4;

#pragma unroll 2
    for (int t = 0; t < T_; t++) {
        float4 c = *(const float4*)(dp + (size_t)t * H_);
        float cur[4] = {c.x, c.y, c.z, c.w};
        unsigned short u[4];
#pragma unroll
        for (int j = 0; j < 4; j++) {
            mem[j] = mem[j] * a1[j] + om[j] * cur[j] - spk[j];
            spk[j] = (mem[j] > 1.0f) ? 1.0f : 0.0f;
            u[j]   = (mem[j] > 1.0f) ? 0x3F80 : 0x0000;
        }
        uint2 w = make_uint2((uint32_t)u[1] << 16 | u[0], (uint32_t)u[3] << 16 | u[2]);
        *(uint2*)(sp + (size_t)t * H_) = w;
    }
}

// ---------------------------------------------------------------------------
// Kernel 2b (phase B): d2^T[32, M] = W2splits[32,1024] @ spk^T. HMMA, roles
// swapped: W2 is the A operand (m=32), spike rows are the B operand (n).
// CTA: 512 spike rows, 8 warps x 64 rows. 2 W2 splits (spikes exact in bf16).
// ---------------------------------------------------------------------------
__global__ __launch_bounds__(256)
void d2_gemm_kernel()
{
    extern __shared__ __align__(1024) char smem[];
    const uint32_t smem_base = smem_to_u32(smem);
    const int tid  = threadIdx.x;
    const int wid  = tid >> 5;
    const int lane = tid & 31;
    const int m0 = blockIdx.x * PB_ROWS;

    // cp.async geometry: spk tile 512x64 bf16 -> 4096 16B chunks, 16/thread
    uint32_t s_sdst[16];
    size_t   s_goff[16];
#pragma unroll
    for (int i = 0; i < 16; i++) {
        int c = tid + i * 256;
        int row = c >> 3, unit = c & 7;
        s_sdst[i] = SWZ128(row * 128 + unit * 16);
        s_goff[i] = (size_t)row * PB_K + unit * 8;
    }
    // W2 tiles: per split 32x64 bf16 -> 256 chunks, 1/thread
    const int wrow = tid >> 3, wunit = tid & 7;
    const uint32_t w_sdst = SWZ128(wrow * 128 + wunit * 16);
    const size_t   w_goff = (size_t)wrow * PB_K + wunit * 8;

    const __nv_bfloat16* spk_base = g_spk + (size_t)m0 * PB_K;

    // ldmatrix addresses
    const int q  = lane >> 3;
    const int rr = lane & 7;
    uint32_t abyte[2];   // W2 (A-operand): mt 0..1
#pragma unroll
    for (int mt = 0; mt < 2; mt++) {
        int row = mt * 16 + (q & 1) * 8 + rr;
        abyte[mt] = (uint32_t)(row * 128 + (q >> 1) * 16);
    }
    uint32_t bbyte[4];   // spikes (B-operand): np 0..3 (n = wid*64 + np*16 ..)
#pragma unroll
    for (int np = 0; np < 4; np++) {
        int row = wid * 64 + np * 16 + (q >> 1) * 8 + rr;
        bbyte[np] = (uint32_t)(row * 128 + (q & 1) * 16);
    }

    float acc[2][8][4];
#pragma unroll
    for (int mt = 0; mt < 2; mt++)
#pragma unroll
        for (int nt = 0; nt < 8; nt++)
#pragma unroll
            for (int i = 0; i < 4; i++) acc[mt][nt][i] = 0.0f;

    // prologue: stages 0,1
#pragma unroll
    for (int pk = 0; pk < 2; pk++) {
        uint32_t sb = smem_base + pk * PB_STAGE;
#pragma unroll
        for (int i = 0; i < 16; i++)
            CP_ASYNC16(sb + s_sdst[i], spk_base + s_goff[i] + pk * PB_BK);
#pragma unroll
        for (int p = 0; p < 2; p++)
            CP_ASYNC16(sb + PB_SPK_B + p * PB_W2_B + w_sdst,
                       &g_W2s[p][0] + w_goff + pk * PB_BK);
        CP_COMMIT();
    }

    for (int k = 0; k < PB_NCH; k++) {
        CP_WAIT1();
        __syncthreads();

        const uint32_t stage = smem_base + (k & 1) * PB_STAGE;
#pragma unroll
        for (int kk = 0; kk < 4; kk++) {
            uint32_t bf[8][2];
#pragma unroll
            for (int np = 0; np < 4; np++) {
                uint32_t byte = bbyte[np] + kk * 32;
                ldsm_x4(bf[np * 2][0], bf[np * 2][1], bf[np * 2 + 1][0], bf[np * 2 + 1][1],
                        stage + SWZ128(byte));
            }
#pragma unroll
            for (int p = 0; p < 2; p++) {
                uint32_t wbase = stage + PB_SPK_B + p * PB_W2_B;
                uint32_t af[2][4];
#pragma unroll
                for (int mt = 0; mt < 2; mt++) {
                    uint32_t byte = abyte[mt] + kk * 32;
                    ldsm_x4(af[mt][0], af[mt][1], af[mt][2], af[mt][3],
                            wbase + SWZ128(byte));
                }
#pragma unroll
                for (int mt = 0; mt < 2; mt++)
#pragma unroll
                    for (int nt = 0; nt < 8; nt++)
                        mma16816(acc[mt][nt], af[mt], bf[nt]);
            }
        }
        __syncthreads();

        if (k + 2 < PB_NCH) {
            uint32_t sb = smem_base + (k & 1) * PB_STAGE;
            int k0 = (k + 2) * PB_BK;
#pragma unroll
            for (int i = 0; i < 16; i++)
                CP_ASYNC16(sb + s_sdst[i], spk_base + s_goff[i] + k0);
#pragma unroll
            for (int p = 0; p < 2; p++)
                CP_ASYNC16(sb + PB_SPK_B + p * PB_W2_B + w_sdst,
                           &g_W2s[p][0] + w_goff + k0);
        }
        CP_COMMIT();
    }

    // epilogue: acc[mt][nt] is d2^T fragment: m-dim = output o, n-dim = spike row
#pragma unroll
    for (int mt = 0; mt < 2; mt++) {
#pragma unroll
        for (int nt = 0; nt < 8; nt++) {
            int o  = mt * 16 + (lane >> 2);
            int n  = wid * 64 + nt * 8 + (lane & 3) * 2;
            size_t gm = (size_t)(m0 + n);
            g_d2[gm * 32 + o]           = acc[mt][nt][0];
            g_d2[(gm + 1) * 32 + o]     = acc[mt][nt][1];
            g_d2[gm * 32 + o + 8]       = acc[mt][nt][2];
            g_d2[(gm + 1) * 32 + o + 8] = acc[mt][nt][3];
        }
    }
}

// ---------------------------------------------------------------------------
// Kernel 2c (phase C): readout EMA + softmax accumulate. One warp per sample.
// ---------------------------------------------------------------------------
__global__ __launch_bounds__(256) void readout_kernel(
    const float* __restrict__ tau2,
    const float* __restrict__ b2,
    float* __restrict__ out)
{
    const int warp = threadIdx.x >> 5;
    const int lane = threadIdx.x & 31;
    const int b = blockIdx.x * 8 + warp;

    float a2 = 0.0f, oma2 = 0.0f, bb = 0.0f, mem2 = 0.0f, accv = 0.0f;
    if (lane < O_) {
        a2 = 1.0f / (1.0f + expf(-tau2[lane]));
        oma2 = 1.0f - a2;
        bb = b2[lane];
    }

    const float* dp = g_d2 + (size_t)b * T_ * 32;
    for (int t = 0; t < T_; t++) {
        float v = dp[(size_t)t * 32 + lane];
        if (lane < O_) mem2 = mem2 * a2 + oma2 * (v + bb);
        float x = (lane < O_) ? mem2 : -CUDART_INF_F;
        float mx = x;
#pragma unroll
        for (int off = 16; off > 0; off >>= 1)
            mx = fmaxf(mx, __shfl_xor_sync(0xffffffffu, mx, off));
        float e = (lane < O_) ? expf(mem2 - mx) : 0.0f;
        float s = e;
#pragma unroll
        for (int off = 16; off > 0; off >>= 1)
            s += __shfl_xor_sync(0xffffffffu, s, off);
        if (t > 10 && lane < O_) accv += e / s;
    }
    if (lane < O_) out[b * O_ + lane] = accv;
}

// ---------------------------------------------------------------------------
extern "C" void kernel_launch(void* const* d_in, const int* in_sizes, int n_in,
                              void* d_out, int out_size)
{
    const float* input = (const float*)d_in[0];  // [B,T,D]
    const float* W1    = (const float*)d_in[1];  // [H,D]
    const float* b1    = (const float*)d_in[2];  // [H]
    const float* tau1  = (const float*)d_in[3];  // [H]
    const float* W2    = (const float*)d_in[4];  // [O,H]
    const float* b2    = (const float*)d_in[5];  // [O]
    const float* tau2  = (const float*)d_in[6];  // [O]
    float* out = (float*)d_out;                  // [B,O]

    cudaFuncSetAttribute(gemm_hmma_kernel,
                         cudaFuncAttributeMaxDynamicSharedMemorySize, SMEM_TOTAL);
    cudaFuncSetAttribute(d2_gemm_kernel,
                         cudaFuncAttributeMaxDynamicSharedMemorySize, PB_SMEM);

    __nv_bfloat16 *a0, *a1, *a2, *w0, *w1s, *w2s, *spkp;
    float *d1p;
    cudaGetSymbolAddress((void**)&a0,   g_A0);
    cudaGetSymbolAddress((void**)&a1,   g_A1);
    cudaGetSymbolAddress((void**)&a2,   g_A2);
    cudaGetSymbolAddress((void**)&w0,   g_B0);
    cudaGetSymbolAddress((void**)&w1s,  g_B1);
    cudaGetSymbolAddress((void**)&w2s,  g_B2);
    cudaGetSymbolAddress((void**)&spkp, g_spk);
    cudaGetSymbolAddress((void**)&d1p,  g_d1);

    {
        long long ng = (long long)M_ * (KP_ / 4);
        int blocks = (int)((ng + 255) / 256);
        split_kernel<<<blocks, 256>>>(input, M_, a0, a1, a2);
    }
    {
        long long ng = (long long)H_ * (KP_ / 4);
        int blocks = (int)((ng + 255) / 256);
        split_kernel<<<blocks, 256>>>(W1, H_, w0, w1s, w2s);
    }
    split_w2_kernel<<<(32 * PB_K + 255) / 256, 256>>>(W2);

    dim3 ggrid(H_ / BN, M_ / BM);  // (8, 500)
    gemm_hmma_kernel<<<ggrid, 256, SMEM_TOTAL>>>(b1);

    lif1_kernel<<<B_, 256>>>(d1p, tau1, spkp);
    d2_gemm_kernel<<<M_ / PB_ROWS, 256, PB_SMEM>>>();   // 125 CTAs
    readout_kernel<<<B_ / 8, 256>>>(tau2, b2, out);
}

// round 5
// speedup vs baseline: 3.6542x; 1.5772x over previous
#include <cuda_runtime.h>
#include <cuda_fp16.h>
#include <cuda_bf16.h>
#include <math_constants.h>
#include <cstdint>

// ---------------- shapes ----------------
#define B_  256
#define T_  250
#define D_  700
#define H_  1024
#define O_  20
#define M_  (B_ * T_)   // 64000
#define KP_ 704         // K padded to multiple of 64

// ---------------- main GEMM tiling ----------------
#define BM 128
#define BN 128
#define BK 64
#define NCHUNK (KP_ / BK)              // 11
#define TILE_B (128 * BK * 2)          // 16384 bytes per operand tile
#define STAGE_B (4 * TILE_B)           // 65536 (A_hi, A_lo, W_hi, W_lo)
#define NSTAGE 3
#define SMEM_TOTAL (NSTAGE * STAGE_B)  // 196608

#define A_SCALE 2048.0f
#define W_SCALE 64.0f
#define INV_SCALE (1.0f / (A_SCALE * W_SCALE))   // 2^-17, exact

// ---------------- phase-B (d2) GEMM tiling ----------------
#define PB_ROWS 512
#define PB_K    1024
#define PB_BK   64
#define PB_NCH  (PB_K / PB_BK)         // 16
#define PB_SPK_B (PB_ROWS * PB_BK * 2) // 65536
#define PB_W2_B  (32 * PB_BK * 2)      // 4096 per split
#define PB_STAGE (PB_SPK_B + 2 * PB_W2_B)   // 73728
#define PB_SMEM  (2 * PB_STAGE)        // 147456

// ---------------- scratch (static device globals; no allocation) ----------------
__device__ float g_d1[(size_t)M_ * H_];
__device__ __half g_Ah[(size_t)M_ * KP_];
__device__ __half g_Al[(size_t)M_ * KP_];
__device__ __half g_Wh[(size_t)H_ * KP_];
__device__ __half g_Wl[(size_t)H_ * KP_];
__device__ __nv_bfloat16 g_spk[(size_t)M_ * H_];      // bf16 spikes (0/1)
__device__ __nv_bfloat16 g_W2s[2][32 * PB_K];          // W2 hi/lo bf16 splits
__device__ float g_d2[(size_t)M_ * 32];                // d2 (padded to 32 outputs)

// ---------------- family-safe PTX helpers ----------------
__device__ __forceinline__ uint32_t smem_to_u32(const void* smem_ptr) {
    uint32_t addr;
    asm("{ .reg .u64 tmp; cvta.to.shared.u64 tmp, %1; cvt.u32.u64 %0, tmp; }"
        : "=r"(addr) : "l"(smem_ptr));
    return addr;
}
#define CP_ASYNC16(dst_u32, src_ptr) \
    asm volatile("cp.async.cg.shared.global [%0], [%1], 16;" \
        :: "r"(dst_u32), "l"(src_ptr))
#define CP_COMMIT() asm volatile("cp.async.commit_group;" ::: "memory")
#define CP_WAIT1()  asm volatile("cp.async.wait_group 1;" ::: "memory")
#define CP_WAIT2()  asm volatile("cp.async.wait_group 2;" ::: "memory")

__device__ __forceinline__ void ldsm_x4(uint32_t& r0, uint32_t& r1,
                                        uint32_t& r2, uint32_t& r3, uint32_t addr) {
    asm volatile("ldmatrix.sync.aligned.m8n8.x4.shared.b16 {%0,%1,%2,%3}, [%4];"
        : "=r"(r0), "=r"(r1), "=r"(r2), "=r"(r3) : "r"(addr));
}
__device__ __forceinline__ void mma16816_f16(float* c, const uint32_t* a, const uint32_t* b) {
    asm volatile(
        "mma.sync.aligned.m16n8k16.row.col.f32.f16.f16.f32 "
        "{%0,%1,%2,%3}, {%4,%5,%6,%7}, {%8,%9}, {%0,%1,%2,%3};"
        : "+f"(c[0]), "+f"(c[1]), "+f"(c[2]), "+f"(c[3])
        : "r"(a[0]), "r"(a[1]), "r"(a[2]), "r"(a[3]), "r"(b[0]), "r"(b[1]));
}
__device__ __forceinline__ void mma16816_bf16(float* c, const uint32_t* a, const uint32_t* b) {
    asm volatile(
        "mma.sync.aligned.m16n8k16.row.col.f32.bf16.bf16.f32 "
        "{%0,%1,%2,%3}, {%4,%5,%6,%7}, {%8,%9}, {%0,%1,%2,%3};"
        : "+f"(c[0]), "+f"(c[1]), "+f"(c[2]), "+f"(c[3])
        : "r"(a[0]), "r"(a[1]), "r"(a[2]), "r"(a[3]), "r"(b[0]), "r"(b[1]));
}
#define SWZ128(o) ((o) ^ (((o) >> 3) & 0x70))

// ---------------------------------------------------------------------------
// Kernel 0: fp32 -> 2x fp16 split with pre-scale. K padded 700->704 w/ zeros.
// ---------------------------------------------------------------------------
__global__ void split2_kernel(const float* __restrict__ src, int rows, float scale,
                              __half* __restrict__ o0, __half* __restrict__ o1)
{
    const int GPR = KP_ / 4;
    long long idx = (long long)blockIdx.x * blockDim.x + threadIdx.x;
    if (idx >= (long long)rows * GPR) return;
    int m  = (int)(idx / GPR);
    int kg = (int)(idx % GPR);
    float a[4] = {0.f, 0.f, 0.f, 0.f};
    if (kg * 4 < D_) {
        float4 v = *(const float4*)(src + (size_t)m * D_ + kg * 4);
        a[0] = v.x * scale; a[1] = v.y * scale; a[2] = v.z * scale; a[3] = v.w * scale;
    }
    unsigned short h0[4], h1[4];
#pragma unroll
    for (int i = 0; i < 4; i++) {
        __half hi = __float2half_rn(a[i]);
        __half lo = __float2half_rn(a[i] - __half2float(hi));
        h0[i] = __half_as_ushort(hi);
        h1[i] = __half_as_ushort(lo);
    }
    size_t off = (size_t)m * KP_ + kg * 4;
    *(uint2*)(o0 + off) = make_uint2((uint32_t)h0[1] << 16 | h0[0], (uint32_t)h0[3] << 16 | h0[2]);
    *(uint2*)(o1 + off) = make_uint2((uint32_t)h1[1] << 16 | h1[0], (uint32_t)h1[3] << 16 | h1[2]);
}

// ---------------------------------------------------------------------------
// Kernel 0b: W2 [20,1024] fp32 -> 2x bf16 splits padded to [32,1024].
// ---------------------------------------------------------------------------
__global__ void split_w2_kernel(const float* __restrict__ W2)
{
    int idx = blockIdx.x * blockDim.x + threadIdx.x;
    if (idx >= 32 * PB_K) return;
    int row = idx / PB_K;
    float v = (row < O_) ? W2[row * H_ + (idx % PB_K)] : 0.0f;
    __nv_bfloat16 hi = __float2bfloat16(v);
    __nv_bfloat16 lo = __float2bfloat16(v - __bfloat162float(hi));
    g_W2s[0][idx] = hi;
    g_W2s[1][idx] = lo;
}

// ---------------------------------------------------------------------------
// Kernel 1: HMMA fp16 GEMM, fp32 emulation via 3 cross-products.
// C[M,H] = (Ah+Al)(Wh+Wl)^T * 2^-17 + bias. BM=BN=128, BK=64, 3-stage cp.async.
// ---------------------------------------------------------------------------
__global__ __launch_bounds__(256)
void gemm_hmma_kernel(const float* __restrict__ bias)
{
    extern __shared__ __align__(1024) char smem[];
    const uint32_t smem_base = smem_to_u32(smem);
    const int tid  = threadIdx.x;
    const int wid  = tid >> 5;
    const int lane = tid & 31;
    const int wm = wid >> 2;
    const int wn = wid & 3;
    const int bm = blockIdx.y * BM;
    const int bn = blockIdx.x * BN;

    uint32_t sdst[4];
    size_t   goff[4];
#pragma unroll
    for (int j = 0; j < 4; j++) {
        int c = tid + j * 256;
        int row = c >> 3, col = c & 7;
        sdst[j] = SWZ128(row * 128 + col * 16);
        goff[j] = (size_t)row * KP_ + col * 8;
    }
    const __half* gsrc[4];
    gsrc[0] = g_Ah + (size_t)bm * KP_;
    gsrc[1] = g_Al + (size_t)bm * KP_;
    gsrc[2] = g_Wh + (size_t)bn * KP_;
    gsrc[3] = g_Wl + (size_t)bn * KP_;

    const int q  = lane >> 3;
    const int rr = lane & 7;
    uint32_t abyte[4];
#pragma unroll
    for (int mt = 0; mt < 4; mt++) {
        int row = wm * 64 + mt * 16 + (q & 1) * 8 + rr;
        abyte[mt] = (uint32_t)(row * 128 + (q >> 1) * 16);
    }
    uint32_t bbyte[2];
#pragma unroll
    for (int np = 0; np < 2; np++) {
        int row = wn * 32 + np * 16 + (q >> 1) * 8 + rr;
        bbyte[np] = (uint32_t)(row * 128 + (q & 1) * 16);
    }

    float acc[4][4][4];
#pragma unroll
    for (int mt = 0; mt < 4; mt++)
#pragma unroll
        for (int nt = 0; nt < 4; nt++)
#pragma unroll
            for (int i = 0; i < 4; i++) acc[mt][nt][i] = 0.0f;

    // prologue: stages 0..2
#pragma unroll
    for (int pk = 0; pk < NSTAGE; pk++) {
        uint32_t sb = smem_base + pk * STAGE_B;
#pragma unroll
        for (int tix = 0; tix < 4; tix++)
#pragma unroll
            for (int j = 0; j < 4; j++)
                CP_ASYNC16(sb + tix * TILE_B + sdst[j], gsrc[tix] + goff[j] + pk * BK);
        CP_COMMIT();
    }

    const int pa[3] = {0, 0, 1};   // hi,hi,lo
    const int pb[3] = {0, 1, 0};   // hi,lo,hi

    int sidx = 0;
    for (int k = 0; k < NCHUNK; k++) {
        CP_WAIT2();
        __syncthreads();

        const uint32_t stage = smem_base + sidx * STAGE_B;
#pragma unroll
        for (int kk = 0; kk < 4; kk++) {
            uint32_t af[2][4][4];
            uint32_t bf[2][4][2];
#pragma unroll
            for (int s = 0; s < 2; s++) {
                uint32_t ab = stage + s * TILE_B;
                uint32_t bb = stage + (2 + s) * TILE_B;
#pragma unroll
                for (int mt = 0; mt < 4; mt++) {
                    uint32_t byte = abyte[mt] + kk * 32;
                    ldsm_x4(af[s][mt][0], af[s][mt][1], af[s][mt][2], af[s][mt][3],
                            ab + SWZ128(byte));
                }
#pragma unroll
                for (int np = 0; np < 2; np++) {
                    uint32_t byte = bbyte[np] + kk * 32;
                    ldsm_x4(bf[s][np * 2][0], bf[s][np * 2][1],
                            bf[s][np * 2 + 1][0], bf[s][np * 2 + 1][1],
                            bb + SWZ128(byte));
                }
            }
#pragma unroll
            for (int p = 0; p < 3; p++)
#pragma unroll
                for (int mt = 0; mt < 4; mt++)
#pragma unroll
                    for (int nt = 0; nt < 4; nt++)
                        mma16816_f16(acc[mt][nt], af[pa[p]][mt], bf[pb[p]][nt]);
        }
        __syncthreads();

        if (k + NSTAGE < NCHUNK) {
            uint32_t sb = smem_base + sidx * STAGE_B;
            int k0 = (k + NSTAGE) * BK;
#pragma unroll
            for (int tix = 0; tix < 4; tix++)
#pragma unroll
                for (int j = 0; j < 4; j++)
                    CP_ASYNC16(sb + tix * TILE_B + sdst[j], gsrc[tix] + goff[j] + k0);
        }
        CP_COMMIT();
        sidx = (sidx == NSTAGE - 1) ? 0 : sidx + 1;
    }

    const int mrow0 = bm + wm * 64;
    const int ncol0 = bn + wn * 32;
    const int lr = lane >> 2;
    const int lc = (lane & 3) * 2;
#pragma unroll
    for (int mt = 0; mt < 4; mt++) {
#pragma unroll
        for (int nt = 0; nt < 4; nt++) {
            int r = mrow0 + mt * 16 + lr;
            int c = ncol0 + nt * 8 + lc;
            float bx = __ldg(bias + c), by = __ldg(bias + c + 1);
            float2 v0 = make_float2(acc[mt][nt][0] * INV_SCALE + bx,
                                    acc[mt][nt][1] * INV_SCALE + by);
            float2 v1 = make_float2(acc[mt][nt][2] * INV_SCALE + bx,
                                    acc[mt][nt][3] * INV_SCALE + by);
            *(float2*)(g_d1 + (size_t)r * H_ + c)       = v0;
            *(float2*)(g_d1 + (size_t)(r + 8) * H_ + c) = v1;
        }
    }
}

// ---------------------------------------------------------------------------
// Kernel 2a: LIF layer-1 chains. CTA per batch sample, thread owns 4 h.
// ---------------------------------------------------------------------------
__global__ __launch_bounds__(256) void lif1_kernel(
    const float* __restrict__ d1,
    const float* __restrict__ tau1,
    __nv_bfloat16* __restrict__ spk_out)
{
    const int b   = blockIdx.x;
    const int tid = threadIdx.x;

    float4 tv = *(const float4*)(tau1 + tid * 4);
    float a1[4], om[4], mem[4], spk[4];
    a1[0] = 1.0f / (1.0f + expf(-tv.x));
    a1[1] = 1.0f / (1.0f + expf(-tv.y));
    a1[2] = 1.0f / (1.0f + expf(-tv.z));
    a1[3] = 1.0f / (1.0f + expf(-tv.w));
#pragma unroll
    for (int j = 0; j < 4; j++) { om[j] = 1.0f - a1[j]; mem[j] = 0.0f; spk[j] = 0.0f; }

    const float* dp = d1 + (size_t)b * T_ * H_ + tid * 4;
    __nv_bfloat16* sp = spk_out + (size_t)b * T_ * H_ + tid * 4;

#pragma unroll 2
    for (int t = 0; t < T_; t++) {
        float4 c = *(const float4*)(dp + (size_t)t * H_);
        float cur[4] = {c.x, c.y, c.z, c.w};
        unsigned short u[4];
#pragma unroll
        for (int j = 0; j < 4; j++) {
            mem[j] = mem[j] * a1[j] + om[j] * cur[j] - spk[j];
            spk[j] = (mem[j] > 1.0f) ? 1.0f : 0.0f;
            u[j]   = (mem[j] > 1.0f) ? 0x3F80 : 0x0000;
        }
        uint2 w = make_uint2((uint32_t)u[1] << 16 | u[0], (uint32_t)u[3] << 16 | u[2]);
        *(uint2*)(sp + (size_t)t * H_) = w;
    }
}

// ---------------------------------------------------------------------------
// Kernel 2b: d2^T[32, M] = W2splits[32,1024] @ spk^T (bf16 HMMA).
// ---------------------------------------------------------------------------
__global__ __launch_bounds__(256)
void d2_gemm_kernel()
{
    extern __shared__ __align__(1024) char smem[];
    const uint32_t smem_base = smem_to_u32(smem);
    const int tid  = threadIdx.x;
    const int wid  = tid >> 5;
    const int lane = tid & 31;
    const int m0 = blockIdx.x * PB_ROWS;

    uint32_t s_sdst[16];
    size_t   s_goff[16];
#pragma unroll
    for (int i = 0; i < 16; i++) {
        int c = tid + i * 256;
        int row = c >> 3, unit = c & 7;
        s_sdst[i] = SWZ128(row * 128 + unit * 16);
        s_goff[i] = (size_t)row * PB_K + unit * 8;
    }
    const int wrow = tid >> 3, wunit = tid & 7;
    const uint32_t w_sdst = SWZ128(wrow * 128 + wunit * 16);
    const size_t   w_goff = (size_t)wrow * PB_K + wunit * 8;

    const __nv_bfloat16* spk_base = g_spk + (size_t)m0 * PB_K;

    const int q  = lane >> 3;
    const int rr = lane & 7;
    uint32_t abyte[2];
#pragma unroll
    for (int mt = 0; mt < 2; mt++) {
        int row = mt * 16 + (q & 1) * 8 + rr;
        abyte[mt] = (uint32_t)(row * 128 + (q >> 1) * 16);
    }
    uint32_t bbyte[4];
#pragma unroll
    for (int np = 0; np < 4; np++) {
        int row = wid * 64 + np * 16 + (q >> 1) * 8 + rr;
        bbyte[np] = (uint32_t)(row * 128 + (q & 1) * 16);
    }

    float acc[2][8][4];
#pragma unroll
    for (int mt = 0; mt < 2; mt++)
#pragma unroll
        for (int nt = 0; nt < 8; nt++)
#pragma unroll
            for (int i = 0; i < 4; i++) acc[mt][nt][i] = 0.0f;

#pragma unroll
    for (int pk = 0; pk < 2; pk++) {
        uint32_t sb = smem_base + pk * PB_STAGE;
#pragma unroll
        for (int i = 0; i < 16; i++)
            CP_ASYNC16(sb + s_sdst[i], spk_base + s_goff[i] + pk * PB_BK);
#pragma unroll
        for (int p = 0; p < 2; p++)
            CP_ASYNC16(sb + PB_SPK_B + p * PB_W2_B + w_sdst,
                       &g_W2s[p][0] + w_goff + pk * PB_BK);
        CP_COMMIT();
    }

    for (int k = 0; k < PB_NCH; k++) {
        CP_WAIT1();
        __syncthreads();

        const uint32_t stage = smem_base + (k & 1) * PB_STAGE;
#pragma unroll
        for (int kk = 0; kk < 4; kk++) {
            uint32_t bf[8][2];
#pragma unroll
            for (int np = 0; np < 4; np++) {
                uint32_t byte = bbyte[np] + kk * 32;
                ldsm_x4(bf[np * 2][0], bf[np * 2][1], bf[np * 2 + 1][0], bf[np * 2 + 1][1],
                        stage + SWZ128(byte));
            }
#pragma unroll
            for (int p = 0; p < 2; p++) {
                uint32_t wbase = stage + PB_SPK_B + p * PB_W2_B;
                uint32_t af[2][4];
#pragma unroll
                for (int mt = 0; mt < 2; mt++) {
                    uint32_t byte = abyte[mt] + kk * 32;
                    ldsm_x4(af[mt][0], af[mt][1], af[mt][2], af[mt][3],
                            wbase + SWZ128(byte));
                }
#pragma unroll
                for (int mt = 0; mt < 2; mt++)
#pragma unroll
                    for (int nt = 0; nt < 8; nt++)
                        mma16816_bf16(acc[mt][nt], af[mt], bf[nt]);
            }
        }
        __syncthreads();

        if (k + 2 < PB_NCH) {
            uint32_t sb = smem_base + (k & 1) * PB_STAGE;
            int k0 = (k + 2) * PB_BK;
#pragma unroll
            for (int i = 0; i < 16; i++)
                CP_ASYNC16(sb + s_sdst[i], spk_base + s_goff[i] + k0);
#pragma unroll
            for (int p = 0; p < 2; p++)
                CP_ASYNC16(sb + PB_SPK_B + p * PB_W2_B + w_sdst,
                           &g_W2s[p][0] + w_goff + k0);
        }
        CP_COMMIT();
    }

#pragma unroll
    for (int mt = 0; mt < 2; mt++) {
#pragma unroll
        for (int nt = 0; nt < 8; nt++) {
            int o  = mt * 16 + (lane >> 2);
            int n  = wid * 64 + nt * 8 + (lane & 3) * 2;
            size_t gm = (size_t)(m0 + n);
            g_d2[gm * 32 + o]           = acc[mt][nt][0];
            g_d2[(gm + 1) * 32 + o]     = acc[mt][nt][1];
            g_d2[gm * 32 + o + 8]       = acc[mt][nt][2];
            g_d2[(gm + 1) * 32 + o + 8] = acc[mt][nt][3];
        }
    }
}

// ---------------------------------------------------------------------------
// Kernel 2c: readout EMA + softmax accumulate. One warp per sample.
// ---------------------------------------------------------------------------
__global__ __launch_bounds__(256) void readout_kernel(
    const float* __restrict__ tau2,
    const float* __restrict__ b2,
    float* __restrict__ out)
{
    const int warp = threadIdx.x >> 5;
    const int lane = threadIdx.x & 31;
    const int b = blockIdx.x * 8 + warp;

    float a2 = 0.0f, oma2 = 0.0f, bb = 0.0f, mem2 = 0.0f, accv = 0.0f;
    if (lane < O_) {
        a2 = 1.0f / (1.0f + expf(-tau2[lane]));
        oma2 = 1.0f - a2;
        bb = b2[lane];
    }

    const float* dp = g_d2 + (size_t)b * T_ * 32;
    for (int t = 0; t < T_; t++) {
        float v = dp[(size_t)t * 32 + lane];
        if (lane < O_) mem2 = mem2 * a2 + oma2 * (v + bb);
        float x = (lane < O_) ? mem2 : -CUDART_INF_F;
        float mx = x;
#pragma unroll
        for (int off = 16; off > 0; off >>= 1)
            mx = fmaxf(mx, __shfl_xor_sync(0xffffffffu, mx, off));
        float e = (lane < O_) ? expf(mem2 - mx) : 0.0f;
        float s = e;
#pragma unroll
        for (int off = 16; off > 0; off >>= 1)
            s += __shfl_xor_sync(0xffffffffu, s, off);
        if (t > 10 && lane < O_) accv += e / s;
    }
    if (lane < O_) out[b * O_ + lane] = accv;
}

// ---------------------------------------------------------------------------
extern "C" void kernel_launch(void* const* d_in, const int* in_sizes, int n_in,
                              void* d_out, int out_size)
{
    const float* input = (const float*)d_in[0];  // [B,T,D]
    const float* W1    = (const float*)d_in[1];  // [H,D]
    const float* b1    = (const float*)d_in[2];  // [H]
    const float* tau1  = (const float*)d_in[3];  // [H]
    const float* W2    = (const float*)d_in[4];  // [O,H]
    const float* b2    = (const float*)d_in[5];  // [O]
    const float* tau2  = (const float*)d_in[6];  // [O]
    float* out = (float*)d_out;                  // [B,O]

    cudaFuncSetAttribute(gemm_hmma_kernel,
                         cudaFuncAttributeMaxDynamicSharedMemorySize, SMEM_TOTAL);
    cudaFuncSetAttribute(d2_gemm_kernel,
                         cudaFuncAttributeMaxDynamicSharedMemorySize, PB_SMEM);

    __half *ah, *al, *wh, *wl;
    __nv_bfloat16 *spkp;
    float *d1p;
    cudaGetSymbolAddress((void**)&ah,   g_Ah);
    cudaGetSymbolAddress((void**)&al,   g_Al);
    cudaGetSymbolAddress((void**)&wh,   g_Wh);
    cudaGetSymbolAddress((void**)&wl,   g_Wl);
    cudaGetSymbolAddress((void**)&spkp, g_spk);
    cudaGetSymbolAddress((void**)&d1p,  g_d1);

    {
        long long ng = (long long)M_ * (KP_ / 4);
        int blocks = (int)((ng + 255) / 256);
        split2_kernel<<<blocks, 256>>>(input, M_, A_SCALE, ah, al);
    }
    {
        long long ng = (long long)H_ * (KP_ / 4);
        int blocks = (int)((ng + 255) / 256);
        split2_kernel<<<blocks, 256>>>(W1, H_, W_SCALE, wh, wl);
    }
    split_w2_kernel<<<(32 * PB_K + 255) / 256, 256>>>(W2);

    dim3 ggrid(H_ / BN, M_ / BM);  // (8, 500)
    gemm_hmma_kernel<<<ggrid, 256, SMEM_TOTAL>>>(b1);

    lif1_kernel<<<B_, 256>>>(d1p, tau1, spkp);
    d2_gemm_kernel<<<M_ / PB_ROWS, 256, PB_SMEM>>>();
    readout_kernel<<<B_ / 8, 256>>>(tau2, b2, out);
}

// round 6
// speedup vs baseline: 3.7824x; 1.0351x over previous
#include <cuda_runtime.h>
#include <cuda_fp16.h>
#include <cuda_bf16.h>
#include <math_constants.h>
#include <cstdint>

// ---------------- shapes ----------------
#define B_  256
#define T_  250
#define D_  700
#define H_  1024
#define O_  20
#define M_  (B_ * T_)   // 64000
#define KP_ 704         // K padded to multiple of 64

// ---------------- main GEMM tiling ----------------
#define BM 128
#define BN 128
#define BK 64
#define NCHUNK (KP_ / BK)              // 11
#define TILE_B (128 * BK * 2)          // 16384 bytes per operand tile
#define STAGE_B (4 * TILE_B)           // 65536 (A_hi, A_lo, W_hi, W_lo)
#define NSTAGE 3
#define SMEM_TOTAL (NSTAGE * STAGE_B)  // 196608

#define A_SCALE 2048.0f
#define W_SCALE 64.0f
#define INV_SCALE (1.0f / (A_SCALE * W_SCALE))   // 2^-17, exact

// ---------------- phase-B (d2) GEMM tiling ----------------
#define PB_ROWS 512
#define PB_K    1024
#define PB_BK   64
#define PB_NCH  (PB_K / PB_BK)         // 16
#define PB_SPKBUF  (PB_ROWS * PB_BK * 2)   // 65536 per buffer
#define PB_W2TILE  (32 * PB_BK * 2)        // 4096 per split
#define PB_W2STAGE (2 * PB_W2TILE)         // 8192
#define PB_SMEM (2 * PB_SPKBUF + 2 * PB_W2STAGE)   // 147456

// ---------------- scratch (static device globals; no allocation) ----------------
__device__ float g_d1[(size_t)M_ * H_];
__device__ __half g_Ah[(size_t)M_ * KP_];
__device__ __half g_Al[(size_t)M_ * KP_];
__device__ __half g_Wh[(size_t)H_ * KP_];
__device__ __half g_Wl[(size_t)H_ * KP_];
__device__ uint32_t g_msk[(size_t)M_ * 32];            // spike bitmasks
__device__ __nv_bfloat16 g_W2s[2][32 * PB_K];          // W2 hi/lo bf16 splits (bit-permuted)
__device__ float g_d2[(size_t)M_ * 32];                // d2 (padded to 32 outputs)

// ---------------- family-safe PTX helpers ----------------
__device__ __forceinline__ uint32_t smem_to_u32(const void* smem_ptr) {
    uint32_t addr;
    asm("{ .reg .u64 tmp; cvta.to.shared.u64 tmp, %1; cvt.u32.u64 %0, tmp; }"
        : "=r"(addr) : "l"(smem_ptr));
    return addr;
}
#define CP_ASYNC16(dst_u32, src_ptr) \
    asm volatile("cp.async.cg.shared.global [%0], [%1], 16;" \
        :: "r"(dst_u32), "l"(src_ptr))
#define CP_COMMIT() asm volatile("cp.async.commit_group;" ::: "memory")
#define CP_WAIT1()  asm volatile("cp.async.wait_group 1;" ::: "memory")
#define CP_WAIT2()  asm volatile("cp.async.wait_group 2;" ::: "memory")

__device__ __forceinline__ void ldsm_x4(uint32_t& r0, uint32_t& r1,
                                        uint32_t& r2, uint32_t& r3, uint32_t addr) {
    asm volatile("ldmatrix.sync.aligned.m8n8.x4.shared.b16 {%0,%1,%2,%3}, [%4];"
        : "=r"(r0), "=r"(r1), "=r"(r2), "=r"(r3) : "r"(addr));
}
__device__ __forceinline__ void mma16816_f16(float* c, const uint32_t* a, const uint32_t* b) {
    asm volatile(
        "mma.sync.aligned.m16n8k16.row.col.f32.f16.f16.f32 "
        "{%0,%1,%2,%3}, {%4,%5,%6,%7}, {%8,%9}, {%0,%1,%2,%3};"
        : "+f"(c[0]), "+f"(c[1]), "+f"(c[2]), "+f"(c[3])
        : "r"(a[0]), "r"(a[1]), "r"(a[2]), "r"(a[3]), "r"(b[0]), "r"(b[1]));
}
__device__ __forceinline__ void mma16816_bf16(float* c, const uint32_t* a, const uint32_t* b) {
    asm volatile(
        "mma.sync.aligned.m16n8k16.row.col.f32.bf16.bf16.f32 "
        "{%0,%1,%2,%3}, {%4,%5,%6,%7}, {%8,%9}, {%0,%1,%2,%3};"
        : "+f"(c[0]), "+f"(c[1]), "+f"(c[2]), "+f"(c[3])
        : "r"(a[0]), "r"(a[1]), "r"(a[2]), "r"(a[3]), "r"(b[0]), "r"(b[1]));
}
#define SWZ128(o) ((o) ^ (((o) >> 3) & 0x70))

// expand 2 spike bits into packed bf16x2 (1.0f / 0.0f halves)
__device__ __forceinline__ uint32_t expand2(uint32_t b) {
    return ((b & 1u) * 0x3F80u) | ((b >> 1) * 0x3F800000u);
}

// ---------------------------------------------------------------------------
// Kernel 0: fp32 -> 2x fp16 split with pre-scale. K padded 700->704 w/ zeros.
// ---------------------------------------------------------------------------
__global__ void split2_kernel(const float* __restrict__ src, int rows, float scale,
                              __half* __restrict__ o0, __half* __restrict__ o1)
{
    const int GPR = KP_ / 4;
    long long idx = (long long)blockIdx.x * blockDim.x + threadIdx.x;
    if (idx >= (long long)rows * GPR) return;
    int m  = (int)(idx / GPR);
    int kg = (int)(idx % GPR);
    float a[4] = {0.f, 0.f, 0.f, 0.f};
    if (kg * 4 < D_) {
        float4 v = *(const float4*)(src + (size_t)m * D_ + kg * 4);
        a[0] = v.x * scale; a[1] = v.y * scale; a[2] = v.z * scale; a[3] = v.w * scale;
    }
    unsigned short h0[4], h1[4];
#pragma unroll
    for (int i = 0; i < 4; i++) {
        __half hi = __float2half_rn(a[i]);
        __half lo = __float2half_rn(a[i] - __half2float(hi));
        h0[i] = __half_as_ushort(hi);
        h1[i] = __half_as_ushort(lo);
    }
    size_t off = (size_t)m * KP_ + kg * 4;
    *(uint2*)(o0 + off) = make_uint2((uint32_t)h0[1] << 16 | h0[0], (uint32_t)h0[3] << 16 | h0[2]);
    *(uint2*)(o1 + off) = make_uint2((uint32_t)h1[1] << 16 | h1[0], (uint32_t)h1[3] << 16 | h1[2]);
}

// ---------------------------------------------------------------------------
// Kernel 0b: W2 -> 2x bf16 splits, PERMUTED to ballot bit order.
// Logical k-position p: word w = p>>5, bit l = p&31; producing warp = w>>2,
// j = w&3; actual hidden unit h = (w>>2)*128 + l*4 + (w&3).
// ---------------------------------------------------------------------------
__global__ void split_w2_kernel(const float* __restrict__ W2)
{
    int idx = blockIdx.x * blockDim.x + threadIdx.x;
    if (idx >= 32 * PB_K) return;
    int o = idx / PB_K;
    int p = idx % PB_K;
    int w = p >> 5, l = p & 31;
    int h = (w >> 2) * 128 + l * 4 + (w & 3);
    float v = (o < O_) ? W2[o * H_ + h] : 0.0f;
    __nv_bfloat16 hi = __float2bfloat16(v);
    __nv_bfloat16 lo = __float2bfloat16(v - __bfloat162float(hi));
    g_W2s[0][idx] = hi;
    g_W2s[1][idx] = lo;
}

// ---------------------------------------------------------------------------
// Kernel 1: HMMA fp16 GEMM, fp32 emulation via 3 cross-products.
// Software-pipelined: hi-fragments double-buffered so LDSM(kk+1) overlaps MMA(kk).
// ---------------------------------------------------------------------------
__global__ __launch_bounds__(256)
void gemm_hmma_kernel(const float* __restrict__ bias)
{
    extern __shared__ __align__(1024) char smem[];
    const uint32_t smem_base = smem_to_u32(smem);
    const int tid  = threadIdx.x;
    const int wid  = tid >> 5;
    const int lane = tid & 31;
    const int wm = wid >> 2;
    const int wn = wid & 3;
    const int bm = blockIdx.y * BM;
    const int bn = blockIdx.x * BN;

    uint32_t sdst[4];
    size_t   goff[4];
#pragma unroll
    for (int j = 0; j < 4; j++) {
        int c = tid + j * 256;
        int row = c >> 3, col = c & 7;
        sdst[j] = SWZ128(row * 128 + col * 16);
        goff[j] = (size_t)row * KP_ + col * 8;
    }
    const __half* gsrc[4];
    gsrc[0] = g_Ah + (size_t)bm * KP_;
    gsrc[1] = g_Al + (size_t)bm * KP_;
    gsrc[2] = g_Wh + (size_t)bn * KP_;
    gsrc[3] = g_Wl + (size_t)bn * KP_;

    const int q  = lane >> 3;
    const int rr = lane & 7;
    uint32_t abyte[4];
#pragma unroll
    for (int mt = 0; mt < 4; mt++) {
        int row = wm * 64 + mt * 16 + (q & 1) * 8 + rr;
        abyte[mt] = (uint32_t)(row * 128 + (q >> 1) * 16);
    }
    uint32_t bbyte[2];
#pragma unroll
    for (int np = 0; np < 2; np++) {
        int row = wn * 32 + np * 16 + (q >> 1) * 8 + rr;
        bbyte[np] = (uint32_t)(row * 128 + (q & 1) * 16);
    }

    float acc[4][4][4];
#pragma unroll
    for (int mt = 0; mt < 4; mt++)
#pragma unroll
        for (int nt = 0; nt < 4; nt++)
#pragma unroll
            for (int i = 0; i < 4; i++) acc[mt][nt][i] = 0.0f;

    // prologue: stages 0..2
#pragma unroll
    for (int pk = 0; pk < NSTAGE; pk++) {
        uint32_t sb = smem_base + pk * STAGE_B;
#pragma unroll
        for (int tix = 0; tix < 4; tix++)
#pragma unroll
            for (int j = 0; j < 4; j++)
                CP_ASYNC16(sb + tix * TILE_B + sdst[j], gsrc[tix] + goff[j] + pk * BK);
        CP_COMMIT();
    }

// load hi fragments (A tile 0, W tile 2) for k-step kk into (A4, B4)
#define LOAD_HI(A4, B4, stg, kk) do { \
    _Pragma("unroll") \
    for (int mt = 0; mt < 4; mt++) \
        ldsm_x4((A4)[mt][0], (A4)[mt][1], (A4)[mt][2], (A4)[mt][3], \
                (stg) + 0 * TILE_B + SWZ128(abyte[mt] + (kk) * 32)); \
    _Pragma("unroll") \
    for (int np = 0; np < 2; np++) \
        ldsm_x4((B4)[np * 2][0], (B4)[np * 2][1], (B4)[np * 2 + 1][0], (B4)[np * 2 + 1][1], \
                (stg) + 2 * TILE_B + SWZ128(bbyte[np] + (kk) * 32)); \
} while (0)
// load lo fragments (A tile 1, W tile 3)
#define LOAD_LO(A4, B4, stg, kk) do { \
    _Pragma("unroll") \
    for (int mt = 0; mt < 4; mt++) \
        ldsm_x4((A4)[mt][0], (A4)[mt][1], (A4)[mt][2], (A4)[mt][3], \
                (stg) + 1 * TILE_B + SWZ128(abyte[mt] + (kk) * 32)); \
    _Pragma("unroll") \
    for (int np = 0; np < 2; np++) \
        ldsm_x4((B4)[np * 2][0], (B4)[np * 2][1], (B4)[np * 2 + 1][0], (B4)[np * 2 + 1][1], \
                (stg) + 3 * TILE_B + SWZ128(bbyte[np] + (kk) * 32)); \
} while (0)
#define MMA_BATCH(A4, B4) do { \
    _Pragma("unroll") \
    for (int mt = 0; mt < 4; mt++) \
        _Pragma("unroll") \
        for (int nt = 0; nt < 4; nt++) \
            mma16816_f16(acc[mt][nt], (A4)[mt], (B4)[nt]); \
} while (0)

    int sidx = 0;
    for (int k = 0; k < NCHUNK; k++) {
        CP_WAIT2();
        __syncthreads();

        const uint32_t stage = smem_base + sidx * STAGE_B;
        uint32_t afh[2][4][4], bfh[2][4][2];   // hi, double-buffered over kk
        uint32_t afl[4][4],    bfl[4][2];      // lo, single

        LOAD_HI(afh[0], bfh[0], stage, 0);
#pragma unroll
        for (int kk = 0; kk < 4; kk++) {
            const int cur = kk & 1;
            LOAD_LO(afl, bfl, stage, kk);
            MMA_BATCH(afh[cur], bfh[cur]);               // hi x hi
            if (kk < 3) LOAD_HI(afh[cur ^ 1], bfh[cur ^ 1], stage, kk + 1);
            MMA_BATCH(afh[cur], bfl);                    // hi x lo
            MMA_BATCH(afl, bfh[cur]);                    // lo x hi
        }
        __syncthreads();

        if (k + NSTAGE < NCHUNK) {
            uint32_t sb = smem_base + sidx * STAGE_B;
            int k0 = (k + NSTAGE) * BK;
#pragma unroll
            for (int tix = 0; tix < 4; tix++)
#pragma unroll
                for (int j = 0; j < 4; j++)
                    CP_ASYNC16(sb + tix * TILE_B + sdst[j], gsrc[tix] + goff[j] + k0);
        }
        CP_COMMIT();
        sidx = (sidx == NSTAGE - 1) ? 0 : sidx + 1;
    }

    const int mrow0 = bm + wm * 64;
    const int ncol0 = bn + wn * 32;
    const int lr = lane >> 2;
    const int lc = (lane & 3) * 2;
#pragma unroll
    for (int mt = 0; mt < 4; mt++) {
#pragma unroll
        for (int nt = 0; nt < 4; nt++) {
            int r = mrow0 + mt * 16 + lr;
            int c = ncol0 + nt * 8 + lc;
            float bx = __ldg(bias + c), by = __ldg(bias + c + 1);
            float2 v0 = make_float2(acc[mt][nt][0] * INV_SCALE + bx,
                                    acc[mt][nt][1] * INV_SCALE + by);
            float2 v1 = make_float2(acc[mt][nt][2] * INV_SCALE + bx,
                                    acc[mt][nt][3] * INV_SCALE + by);
            *(float2*)(g_d1 + (size_t)r * H_ + c)       = v0;
            *(float2*)(g_d1 + (size_t)(r + 8) * H_ + c) = v1;
        }
    }
}

// ---------------------------------------------------------------------------
// Kernel 2a: LIF layer-1 chains -> spike BITMASKS via ballot.
// Word layout: word w = warp*4 + j holds, at bit l, the spike of
// h = warp*128 + l*4 + j (matches split_w2 permutation).
// ---------------------------------------------------------------------------
__global__ __launch_bounds__(256) void lif1_kernel(
    const float* __restrict__ d1,
    const float* __restrict__ tau1)
{
    const int b    = blockIdx.x;
    const int tid  = threadIdx.x;
    const int warp = tid >> 5;
    const int lane = tid & 31;

    float4 tv = *(const float4*)(tau1 + tid * 4);
    float a1[4], om[4], mem[4], spk[4];
    a1[0] = 1.0f / (1.0f + expf(-tv.x));
    a1[1] = 1.0f / (1.0f + expf(-tv.y));
    a1[2] = 1.0f / (1.0f + expf(-tv.z));
    a1[3] = 1.0f / (1.0f + expf(-tv.w));
#pragma unroll
    for (int j = 0; j < 4; j++) { om[j] = 1.0f - a1[j]; mem[j] = 0.0f; spk[j] = 0.0f; }

    const float* dp = d1 + (size_t)b * T_ * H_ + tid * 4;
    uint32_t* mp = g_msk + (size_t)b * T_ * 32 + warp * 4;

    float4 nx = *(const float4*)dp;
    for (int t = 0; t < T_; t++) {
        float cur[4] = {nx.x, nx.y, nx.z, nx.w};
        if (t + 1 < T_) nx = *(const float4*)(dp + (size_t)(t + 1) * H_);

        uint32_t bits0, bits1, bits2, bits3;
#pragma unroll
        for (int j = 0; j < 4; j++) {
            mem[j] = mem[j] * a1[j] + om[j] * cur[j] - spk[j];
            spk[j] = (mem[j] > 1.0f) ? 1.0f : 0.0f;
        }
        bits0 = __ballot_sync(0xffffffffu, mem[0] > 1.0f);
        bits1 = __ballot_sync(0xffffffffu, mem[1] > 1.0f);
        bits2 = __ballot_sync(0xffffffffu, mem[2] > 1.0f);
        bits3 = __ballot_sync(0xffffffffu, mem[3] > 1.0f);
        if (lane < 4) {
            uint32_t w = (lane == 0) ? bits0 : (lane == 1) ? bits1
                       : (lane == 2) ? bits2 : bits3;
            mp[(size_t)t * 32 + lane] = w;
        }
    }
}

// ---------------------------------------------------------------------------
// Kernel 2b: d2^T = W2splits[32,1024] @ spk^T. Spikes expanded from bitmasks
// into smem bf16 tiles; W2 (permuted) via 2-stage cp.async.
// ---------------------------------------------------------------------------
__global__ __launch_bounds__(256)
void d2_gemm_kernel()
{
    extern __shared__ __align__(1024) char smem[];
    const uint32_t smem_base = smem_to_u32(smem);
    const int tid  = threadIdx.x;
    const int wid  = tid >> 5;
    const int lane = tid & 31;
    const int m0 = blockIdx.x * PB_ROWS;

    // expansion geometry: idx = tid + i*256 -> row r = idx>>1, word-half wq = idx&1
    uint32_t ebase[4];
    const uint32_t* mrow[4];
#pragma unroll
    for (int i = 0; i < 4; i++) {
        int idx = tid + i * 256;
        int r = idx >> 1, wq = idx & 1;
        ebase[i] = (uint32_t)(r * 128 + wq * 64);
        mrow[i]  = g_msk + (size_t)(m0 + r) * 32 + wq;
    }

    // W2 cp.async geometry
    const int wrow = tid >> 3, wunit = tid & 7;
    const uint32_t w_sdst = SWZ128(wrow * 128 + wunit * 16);
    const size_t   w_goff = (size_t)wrow * PB_K + wunit * 8;
    const uint32_t w2smem = smem_base + 2 * PB_SPKBUF;

    // ldmatrix addresses
    const int q  = lane >> 3;
    const int rr = lane & 7;
    uint32_t abyte[2];
#pragma unroll
    for (int mt = 0; mt < 2; mt++) {
        int row = mt * 16 + (q & 1) * 8 + rr;
        abyte[mt] = (uint32_t)(row * 128 + (q >> 1) * 16);
    }
    uint32_t bbyte[4];
#pragma unroll
    for (int np = 0; np < 4; np++) {
        int row = wid * 64 + np * 16 + (q >> 1) * 8 + rr;
        bbyte[np] = (uint32_t)(row * 128 + (q & 1) * 16);
    }

    float acc[2][8][4];
#pragma unroll
    for (int mt = 0; mt < 2; mt++)
#pragma unroll
        for (int nt = 0; nt < 8; nt++)
#pragma unroll
            for (int i = 0; i < 4; i++) acc[mt][nt][i] = 0.0f;

    // prologue: W2 stages 0,1 + masks for chunk 0
#pragma unroll
    for (int pk = 0; pk < 2; pk++) {
#pragma unroll
        for (int p = 0; p < 2; p++)
            CP_ASYNC16(w2smem + pk * PB_W2STAGE + p * PB_W2TILE + w_sdst,
                       &g_W2s[p][0] + w_goff + pk * PB_BK);
        CP_COMMIT();
    }
    uint32_t mcur[4], mnxt[4];
#pragma unroll
    for (int i = 0; i < 4; i++) mcur[i] = mrow[i][0];

    for (int kc = 0; kc < PB_NCH; kc++) {
        __syncthreads();   // all warps done reading spkbuf[kc&1] (chunk kc-2)

        // expand masks -> spk bf16 tile
        char* sb = smem + (kc & 1) * PB_SPKBUF;
#pragma unroll
        for (int i = 0; i < 4; i++) {
            uint32_t W = mcur[i];
#pragma unroll
            for (int g = 0; g < 4; g++) {
                uint4 u;
                u.x = expand2((W >> (g * 8 + 0)) & 3u);
                u.y = expand2((W >> (g * 8 + 2)) & 3u);
                u.z = expand2((W >> (g * 8 + 4)) & 3u);
                u.w = expand2((W >> (g * 8 + 6)) & 3u);
                *(uint4*)(sb + SWZ128(ebase[i] + g * 16)) = u;
            }
        }
        CP_WAIT1();
        __syncthreads();   // expansion + W2 stage visible

        const uint32_t spkb = smem_base + (kc & 1) * PB_SPKBUF;
        const uint32_t w2b  = w2smem + (kc & 1) * PB_W2STAGE;
#pragma unroll
        for (int kk = 0; kk < 4; kk++) {
            uint32_t bf[8][2];
#pragma unroll
            for (int np = 0; np < 4; np++)
                ldsm_x4(bf[np * 2][0], bf[np * 2][1], bf[np * 2 + 1][0], bf[np * 2 + 1][1],
                        spkb + SWZ128(bbyte[np] + kk * 32));
#pragma unroll
            for (int p = 0; p < 2; p++) {
                uint32_t af[2][4];
#pragma unroll
                for (int mt = 0; mt < 2; mt++)
                    ldsm_x4(af[mt][0], af[mt][1], af[mt][2], af[mt][3],
                            w2b + p * PB_W2TILE + SWZ128(abyte[mt] + kk * 32));
#pragma unroll
                for (int mt = 0; mt < 2; mt++)
#pragma unroll
                    for (int nt = 0; nt < 8; nt++)
                        mma16816_bf16(acc[mt][nt], af[mt], bf[nt]);
            }
        }

        if (kc + 2 < PB_NCH) {
#pragma unroll
            for (int p = 0; p < 2; p++)
                CP_ASYNC16(w2smem + (kc & 1) * PB_W2STAGE + p * PB_W2TILE + w_sdst,
                           &g_W2s[p][0] + w_goff + (kc + 2) * PB_BK);
        }
        CP_COMMIT();
        if (kc + 1 < PB_NCH) {
#pragma unroll
            for (int i = 0; i < 4; i++) mnxt[i] = mrow[i][(kc + 1) * 2];
#pragma unroll
            for (int i = 0; i < 4; i++) mcur[i] = mnxt[i];
        }
    }

#pragma unroll
    for (int mt = 0; mt < 2; mt++) {
#pragma unroll
        for (int nt = 0; nt < 8; nt++) {
            int o  = mt * 16 + (lane >> 2);
            int n  = wid * 64 + nt * 8 + (lane & 3) * 2;
            size_t gm = (size_t)(m0 + n);
            g_d2[gm * 32 + o]           = acc[mt][nt][0];
            g_d2[(gm + 1) * 32 + o]     = acc[mt][nt][1];
            g_d2[gm * 32 + o + 8]       = acc[mt][nt][2];
            g_d2[(gm + 1) * 32 + o + 8] = acc[mt][nt][3];
        }
    }
}

// ---------------------------------------------------------------------------
// Kernel 2c: readout EMA + softmax accumulate (max-free; |mem2|<<88 so safe).
// ---------------------------------------------------------------------------
__global__ __launch_bounds__(256) void readout_kernel(
    const float* __restrict__ tau2,
    const float* __restrict__ b2,
    float* __restrict__ out)
{
    const int warp = threadIdx.x >> 5;
    const int lane = threadIdx.x & 31;
    const int b = blockIdx.x * 8 + warp;

    float a2 = 0.0f, oma2 = 0.0f, bb = 0.0f, mem2 = 0.0f, accv = 0.0f;
    if (lane < O_) {
        a2 = 1.0f / (1.0f + expf(-tau2[lane]));
        oma2 = 1.0f - a2;
        bb = b2[lane];
    }

    const float* dp = g_d2 + (size_t)b * T_ * 32;
    float v = dp[lane];
    for (int t = 0; t < T_; t++) {
        float vn = (t + 1 < T_) ? dp[(size_t)(t + 1) * 32 + lane] : 0.0f;
        if (lane < O_) mem2 = mem2 * a2 + oma2 * (v + bb);
        float e = (lane < O_) ? expf(mem2) : 0.0f;
        float s = e;
#pragma unroll
        for (int off = 16; off > 0; off >>= 1)
            s += __shfl_xor_sync(0xffffffffu, s, off);
        if (t > 10 && lane < O_) accv += e / s;
        v = vn;
    }
    if (lane < O_) out[b * O_ + lane] = accv;
}

// ---------------------------------------------------------------------------
extern "C" void kernel_launch(void* const* d_in, const int* in_sizes, int n_in,
                              void* d_out, int out_size)
{
    const float* input = (const float*)d_in[0];  // [B,T,D]
    const float* W1    = (const float*)d_in[1];  // [H,D]
    const float* b1    = (const float*)d_in[2];  // [H]
    const float* tau1  = (const float*)d_in[3];  // [H]
    const float* W2    = (const float*)d_in[4];  // [O,H]
    const float* b2    = (const float*)d_in[5];  // [O]
    const float* tau2  = (const float*)d_in[6];  // [O]
    float* out = (float*)d_out;                  // [B,O]

    cudaFuncSetAttribute(gemm_hmma_kernel,
                         cudaFuncAttributeMaxDynamicSharedMemorySize, SMEM_TOTAL);
    cudaFuncSetAttribute(d2_gemm_kernel,
                         cudaFuncAttributeMaxDynamicSharedMemorySize, PB_SMEM);

    __half *ah, *al, *wh, *wl;
    float *d1p;
    cudaGetSymbolAddress((void**)&ah,  g_Ah);
    cudaGetSymbolAddress((void**)&al,  g_Al);
    cudaGetSymbolAddress((void**)&wh,  g_Wh);
    cudaGetSymbolAddress((void**)&wl,  g_Wl);
    cudaGetSymbolAddress((void**)&d1p, g_d1);

    {
        long long ng = (long long)M_ * (KP_ / 4);
        int blocks = (int)((ng + 255) / 256);
        split2_kernel<<<blocks, 256>>>(input, M_, A_SCALE, ah, al);
    }
    {
        long long ng = (long long)H_ * (KP_ / 4);
        int blocks = (int)((ng + 255) / 256);
        split2_kernel<<<blocks, 256>>>(W1, H_, W_SCALE, wh, wl);
    }
    split_w2_kernel<<<(32 * PB_K + 255) / 256, 256>>>(W2);

    dim3 ggrid(H_ / BN, M_ / BM);  // (8, 500)
    gemm_hmma_kernel<<<ggrid, 256, SMEM_TOTAL>>>(b1);

    lif1_kernel<<<B_, 256>>>(d1p, tau1);
    d2_gemm_kernel<<<M_ / PB_ROWS, 256, PB_SMEM>>>();
    readout_kernel<<<B_ / 8, 256>>>(tau2, b2, out);
}

// round 7
// speedup vs baseline: 4.0279x; 1.0649x over previous
#include <cuda_runtime.h>
#include <cuda_fp16.h>
#include <cuda_bf16.h>
#include <math_constants.h>
#include <cstdint>

// ---------------- shapes ----------------
#define B_  256
#define T_  250
#define D_  700
#define H_  1024
#define O_  20
#define M_  (B_ * T_)   // 64000
#define KP_ 704         // K padded to multiple of 64

// ---------------- main GEMM tiling ----------------
#define BM 128
#define BN 64
#define BK 64
#define NCHUNK (KP_ / BK)              // 11
#define A_TILE_B (BM * BK * 2)         // 16384
#define W_TILE_B (BN * BK * 2)         // 8192
#define STAGE_B (2 * A_TILE_B + 2 * W_TILE_B)  // 49152
#define NSTAGE 2
#define SMEM_TOTAL (NSTAGE * STAGE_B)  // 98304  -> 2 CTAs/SM

#define A_SCALE 2048.0f
#define W_SCALE 64.0f
#define INV_SCALE (1.0f / (A_SCALE * W_SCALE))   // 2^-17, exact

// ---------------- phase-B (d2) GEMM tiling ----------------
#define PB_ROWS 256
#define PB_K    1024
#define PB_BK   64
#define PB_NCH  (PB_K / PB_BK)             // 16
#define PB_SPKBUF  (PB_ROWS * PB_BK * 2)   // 32768 per buffer
#define PB_W2TILE  (32 * PB_BK * 2)        // 4096 per split
#define PB_W2STAGE (2 * PB_W2TILE)         // 8192
#define PB_SMEM (2 * PB_SPKBUF + 2 * PB_W2STAGE)   // 81920

// ---------------- scratch (static device globals; no allocation) ----------------
__device__ float g_d1[(size_t)M_ * H_];
__device__ __half g_Ah[(size_t)M_ * KP_];
__device__ __half g_Al[(size_t)M_ * KP_];
__device__ __half g_Wh[(size_t)H_ * KP_];
__device__ __half g_Wl[(size_t)H_ * KP_];
__device__ uint32_t g_msk[(size_t)M_ * 32];            // spike bitmasks
__device__ __nv_bfloat16 g_W2s[2][32 * PB_K];          // W2 hi/lo bf16 splits (bit-permuted)
__device__ float g_d2[(size_t)M_ * 32];                // d2 (padded to 32 outputs)

// ---------------- family-safe PTX helpers ----------------
__device__ __forceinline__ uint32_t smem_to_u32(const void* smem_ptr) {
    uint32_t addr;
    asm("{ .reg .u64 tmp; cvta.to.shared.u64 tmp, %1; cvt.u32.u64 %0, tmp; }"
        : "=r"(addr) : "l"(smem_ptr));
    return addr;
}
#define CP_ASYNC16(dst_u32, src_ptr) \
    asm volatile("cp.async.cg.shared.global [%0], [%1], 16;" \
        :: "r"(dst_u32), "l"(src_ptr))
#define CP_COMMIT() asm volatile("cp.async.commit_group;" ::: "memory")
#define CP_WAIT1()  asm volatile("cp.async.wait_group 1;" ::: "memory")

__device__ __forceinline__ void ldsm_x4(uint32_t& r0, uint32_t& r1,
                                        uint32_t& r2, uint32_t& r3, uint32_t addr) {
    asm volatile("ldmatrix.sync.aligned.m8n8.x4.shared.b16 {%0,%1,%2,%3}, [%4];"
        : "=r"(r0), "=r"(r1), "=r"(r2), "=r"(r3) : "r"(addr));
}
__device__ __forceinline__ void mma16816_f16(float* c, const uint32_t* a, const uint32_t* b) {
    asm volatile(
        "mma.sync.aligned.m16n8k16.row.col.f32.f16.f16.f32 "
        "{%0,%1,%2,%3}, {%4,%5,%6,%7}, {%8,%9}, {%0,%1,%2,%3};"
        : "+f"(c[0]), "+f"(c[1]), "+f"(c[2]), "+f"(c[3])
        : "r"(a[0]), "r"(a[1]), "r"(a[2]), "r"(a[3]), "r"(b[0]), "r"(b[1]));
}
__device__ __forceinline__ void mma16816_bf16(float* c, const uint32_t* a, const uint32_t* b) {
    asm volatile(
        "mma.sync.aligned.m16n8k16.row.col.f32.bf16.bf16.f32 "
        "{%0,%1,%2,%3}, {%4,%5,%6,%7}, {%8,%9}, {%0,%1,%2,%3};"
        : "+f"(c[0]), "+f"(c[1]), "+f"(c[2]), "+f"(c[3])
        : "r"(a[0]), "r"(a[1]), "r"(a[2]), "r"(a[3]), "r"(b[0]), "r"(b[1]));
}
#define SWZ128(o) ((o) ^ (((o) >> 3) & 0x70))

// expand 2 spike bits into packed bf16x2 (1.0f / 0.0f halves)
__device__ __forceinline__ uint32_t expand2(uint32_t b) {
    return ((b & 1u) * 0x3F80u) | ((b >> 1) * 0x3F800000u);
}

// ---------------------------------------------------------------------------
// Kernel 0: fp32 -> 2x fp16 split with pre-scale. K padded 700->704 w/ zeros.
// ---------------------------------------------------------------------------
__global__ void split2_kernel(const float* __restrict__ src, int rows, float scale,
                              __half* __restrict__ o0, __half* __restrict__ o1)
{
    const int GPR = KP_ / 4;
    long long idx = (long long)blockIdx.x * blockDim.x + threadIdx.x;
    if (idx >= (long long)rows * GPR) return;
    int m  = (int)(idx / GPR);
    int kg = (int)(idx % GPR);
    float a[4] = {0.f, 0.f, 0.f, 0.f};
    if (kg * 4 < D_) {
        float4 v = *(const float4*)(src + (size_t)m * D_ + kg * 4);
        a[0] = v.x * scale; a[1] = v.y * scale; a[2] = v.z * scale; a[3] = v.w * scale;
    }
    unsigned short h0[4], h1[4];
#pragma unroll
    for (int i = 0; i < 4; i++) {
        __half hi = __float2half_rn(a[i]);
        __half lo = __float2half_rn(a[i] - __half2float(hi));
        h0[i] = __half_as_ushort(hi);
        h1[i] = __half_as_ushort(lo);
    }
    size_t off = (size_t)m * KP_ + kg * 4;
    *(uint2*)(o0 + off) = make_uint2((uint32_t)h0[1] << 16 | h0[0], (uint32_t)h0[3] << 16 | h0[2]);
    *(uint2*)(o1 + off) = make_uint2((uint32_t)h1[1] << 16 | h1[0], (uint32_t)h1[3] << 16 | h1[2]);
}

// ---------------------------------------------------------------------------
// Kernel 0b: W2 -> 2x bf16 splits, PERMUTED to ballot bit order.
// h = (w>>2)*128 + l*4 + (w&3) for word w = p>>5, bit l = p&31.
// ---------------------------------------------------------------------------
__global__ void split_w2_kernel(const float* __restrict__ W2)
{
    int idx = blockIdx.x * blockDim.x + threadIdx.x;
    if (idx >= 32 * PB_K) return;
    int o = idx / PB_K;
    int p = idx % PB_K;
    int w = p >> 5, l = p & 31;
    int h = (w >> 2) * 128 + l * 4 + (w & 3);
    float v = (o < O_) ? W2[o * H_ + h] : 0.0f;
    __nv_bfloat16 hi = __float2bfloat16(v);
    __nv_bfloat16 lo = __float2bfloat16(v - __bfloat162float(hi));
    g_W2s[0][idx] = hi;
    g_W2s[1][idx] = lo;
}

// ---------------------------------------------------------------------------
// Kernel 1: HMMA fp16 GEMM, fp32 emulation via 3 cross-products.
// BM=128, BN=64, BK=64, 2-stage cp.async, 96KB smem -> 2 CTAs/SM.
// 8 warps in 4(m) x 2(n); warp tile 32x32.
// ---------------------------------------------------------------------------
__global__ __launch_bounds__(256, 2)
void gemm_hmma_kernel(const float* __restrict__ bias)
{
    extern __shared__ __align__(1024) char smem[];
    const uint32_t smem_base = smem_to_u32(smem);
    const int tid  = threadIdx.x;
    const int wid  = tid >> 5;
    const int lane = tid & 31;
    const int wm = wid >> 1;       // 0..3 (m)
    const int wn = wid & 1;        // 0..1 (n)
    const int bm = blockIdx.y * BM;
    const int bn = blockIdx.x * BN;

    // cp.async geometry. A tile (128 rows x 128B): 1024 chunks, 4/thread.
    uint32_t sdstA[4];
    size_t   goffA[4];
#pragma unroll
    for (int j = 0; j < 4; j++) {
        int c = tid + j * 256;
        int row = c >> 3, unit = c & 7;
        sdstA[j] = SWZ128(row * 128 + unit * 16);
        goffA[j] = (size_t)row * KP_ + unit * 8;
    }
    // W tile (64 rows x 128B): 512 chunks, 2/thread.
    uint32_t sdstW[2];
    size_t   goffW[2];
#pragma unroll
    for (int j = 0; j < 2; j++) {
        int c = tid + j * 256;
        int row = c >> 3, unit = c & 7;
        sdstW[j] = SWZ128(row * 128 + unit * 16);
        goffW[j] = (size_t)row * KP_ + unit * 8;
    }
    const __half* Asrc[2] = { g_Ah + (size_t)bm * KP_, g_Al + (size_t)bm * KP_ };
    const __half* Wsrc[2] = { g_Wh + (size_t)bn * KP_, g_Wl + (size_t)bn * KP_ };

    // ldmatrix per-lane addresses
    const int q  = lane >> 3;
    const int rr = lane & 7;
    uint32_t abyte[2];             // A: mt 0..1, 16 rows each
#pragma unroll
    for (int mt = 0; mt < 2; mt++) {
        int row = wm * 32 + mt * 16 + (q & 1) * 8 + rr;
        abyte[mt] = (uint32_t)(row * 128 + (q >> 1) * 16);
    }
    uint32_t bbyte[2];             // W: np 0..1, 16 rows each (-> nt pairs)
#pragma unroll
    for (int np = 0; np < 2; np++) {
        int row = wn * 32 + np * 16 + (q >> 1) * 8 + rr;
        bbyte[np] = (uint32_t)(row * 128 + (q & 1) * 16);
    }

    float acc[2][4][4];
#pragma unroll
    for (int mt = 0; mt < 2; mt++)
#pragma unroll
        for (int nt = 0; nt < 4; nt++)
#pragma unroll
            for (int i = 0; i < 4; i++) acc[mt][nt][i] = 0.0f;

#define GEMM_LOAD_CHUNK(sb, k0) do { \
    _Pragma("unroll") \
    for (int s = 0; s < 2; s++) { \
        _Pragma("unroll") \
        for (int j = 0; j < 4; j++) \
            CP_ASYNC16((sb) + s * A_TILE_B + sdstA[j], Asrc[s] + goffA[j] + (k0)); \
        _Pragma("unroll") \
        for (int j = 0; j < 2; j++) \
            CP_ASYNC16((sb) + 2 * A_TILE_B + s * W_TILE_B + sdstW[j], \
                       Wsrc[s] + goffW[j] + (k0)); \
    } \
} while (0)

    // prologue: stages 0,1
    GEMM_LOAD_CHUNK(smem_base, 0);
    CP_COMMIT();
    GEMM_LOAD_CHUNK(smem_base + STAGE_B, BK);
    CP_COMMIT();

    for (int k = 0; k < NCHUNK; k++) {
        CP_WAIT1();
        __syncthreads();

        const uint32_t stage = smem_base + (k & 1) * STAGE_B;
#pragma unroll
        for (int kk = 0; kk < 4; kk++) {
            uint32_t af[2][2][4];   // [split][mt]
            uint32_t bf[2][4][2];   // [split][nt]
#pragma unroll
            for (int s = 0; s < 2; s++) {
#pragma unroll
                for (int mt = 0; mt < 2; mt++)
                    ldsm_x4(af[s][mt][0], af[s][mt][1], af[s][mt][2], af[s][mt][3],
                            stage + s * A_TILE_B + SWZ128(abyte[mt] + kk * 32));
#pragma unroll
                for (int np = 0; np < 2; np++)
                    ldsm_x4(bf[s][np * 2][0], bf[s][np * 2][1],
                            bf[s][np * 2 + 1][0], bf[s][np * 2 + 1][1],
                            stage + 2 * A_TILE_B + s * W_TILE_B
                                  + SWZ128(bbyte[np] + kk * 32));
            }
            const int pa[3] = {0, 0, 1};
            const int pb[3] = {0, 1, 0};
#pragma unroll
            for (int p = 0; p < 3; p++)
#pragma unroll
                for (int mt = 0; mt < 2; mt++)
#pragma unroll
                    for (int nt = 0; nt < 4; nt++)
                        mma16816_f16(acc[mt][nt], af[pa[p]][mt], bf[pb[p]][nt]);
        }
        __syncthreads();

        if (k + NSTAGE < NCHUNK) {
            GEMM_LOAD_CHUNK(smem_base + (k & 1) * STAGE_B, (k + NSTAGE) * BK);
        }
        CP_COMMIT();
    }

    const int mrow0 = bm + wm * 32;
    const int ncol0 = bn + wn * 32;
    const int lr = lane >> 2;
    const int lc = (lane & 3) * 2;
#pragma unroll
    for (int mt = 0; mt < 2; mt++) {
#pragma unroll
        for (int nt = 0; nt < 4; nt++) {
            int r = mrow0 + mt * 16 + lr;
            int c = ncol0 + nt * 8 + lc;
            float bx = __ldg(bias + c), by = __ldg(bias + c + 1);
            float2 v0 = make_float2(acc[mt][nt][0] * INV_SCALE + bx,
                                    acc[mt][nt][1] * INV_SCALE + by);
            float2 v1 = make_float2(acc[mt][nt][2] * INV_SCALE + bx,
                                    acc[mt][nt][3] * INV_SCALE + by);
            *(float2*)(g_d1 + (size_t)r * H_ + c)       = v0;
            *(float2*)(g_d1 + (size_t)(r + 8) * H_ + c) = v1;
        }
    }
}

// ---------------------------------------------------------------------------
// Kernel 2a: LIF layer-1 chains -> spike BITMASKS via ballot.
// 512 CTAs x 128 threads: CTA = (sample b, half of H). Word layout preserved:
// word w = gwarp*4 + j holds at bit l the spike of h = gwarp*128 + l*4 + j.
// ---------------------------------------------------------------------------
__global__ __launch_bounds__(128) void lif1_kernel(
    const float* __restrict__ d1,
    const float* __restrict__ tau1)
{
    const int b    = blockIdx.x >> 1;
    const int half = blockIdx.x & 1;
    const int tid  = threadIdx.x;
    const int wl   = tid >> 5;          // warp within CTA (0..3)
    const int lane = tid & 31;
    const int h0   = half * 512 + tid * 4;

    float4 tv = *(const float4*)(tau1 + h0);
    float a1[4], om[4], mem[4], spk[4];
    a1[0] = 1.0f / (1.0f + expf(-tv.x));
    a1[1] = 1.0f / (1.0f + expf(-tv.y));
    a1[2] = 1.0f / (1.0f + expf(-tv.z));
    a1[3] = 1.0f / (1.0f + expf(-tv.w));
#pragma unroll
    for (int j = 0; j < 4; j++) { om[j] = 1.0f - a1[j]; mem[j] = 0.0f; spk[j] = 0.0f; }

    const float* dp = d1 + (size_t)b * T_ * H_ + h0;
    uint32_t* mp = g_msk + (size_t)b * T_ * 32 + (half * 4 + wl) * 4;

    float4 nx = *(const float4*)dp;
    for (int t = 0; t < T_; t++) {
        float cur[4] = {nx.x, nx.y, nx.z, nx.w};
        if (t + 1 < T_) nx = *(const float4*)(dp + (size_t)(t + 1) * H_);

        uint32_t bits0, bits1, bits2, bits3;
#pragma unroll
        for (int j = 0; j < 4; j++) {
            mem[j] = mem[j] * a1[j] + om[j] * cur[j] - spk[j];
            spk[j] = (mem[j] > 1.0f) ? 1.0f : 0.0f;
        }
        bits0 = __ballot_sync(0xffffffffu, mem[0] > 1.0f);
        bits1 = __ballot_sync(0xffffffffu, mem[1] > 1.0f);
        bits2 = __ballot_sync(0xffffffffu, mem[2] > 1.0f);
        bits3 = __ballot_sync(0xffffffffu, mem[3] > 1.0f);
        if (lane < 4) {
            uint32_t w = (lane == 0) ? bits0 : (lane == 1) ? bits1
                       : (lane == 2) ? bits2 : bits3;
            mp[(size_t)t * 32 + lane] = w;
        }
    }
}

// ---------------------------------------------------------------------------
// Kernel 2b: d2^T = W2splits[32,1024] @ spk^T. Bitmask-expanded spikes.
// PB_ROWS=256 -> 250 CTAs, 80KB smem, 2/SM. 8 warps x 32 rows each.
// ---------------------------------------------------------------------------
__global__ __launch_bounds__(256, 2)
void d2_gemm_kernel()
{
    extern __shared__ __align__(1024) char smem[];
    const uint32_t smem_base = smem_to_u32(smem);
    const int tid  = threadIdx.x;
    const int wid  = tid >> 5;
    const int lane = tid & 31;
    const int m0 = blockIdx.x * PB_ROWS;

    // expansion geometry: idx = tid + i*256 -> row r = idx>>1, word wq = idx&1
    uint32_t ebase[2];
    const uint32_t* mrow[2];
#pragma unroll
    for (int i = 0; i < 2; i++) {
        int idx = tid + i * 256;
        int r = idx >> 1, wq = idx & 1;
        ebase[i] = (uint32_t)(r * 128 + wq * 64);
        mrow[i]  = g_msk + (size_t)(m0 + r) * 32 + wq;
    }

    // W2 cp.async geometry
    const int wrow = tid >> 3, wunit = tid & 7;
    const uint32_t w_sdst = SWZ128(wrow * 128 + wunit * 16);
    const size_t   w_goff = (size_t)wrow * PB_K + wunit * 8;
    const uint32_t w2smem = smem_base + 2 * PB_SPKBUF;

    // ldmatrix addresses
    const int q  = lane >> 3;
    const int rr = lane & 7;
    uint32_t abyte[2];
#pragma unroll
    for (int mt = 0; mt < 2; mt++) {
        int row = mt * 16 + (q & 1) * 8 + rr;
        abyte[mt] = (uint32_t)(row * 128 + (q >> 1) * 16);
    }
    uint32_t bbyte[2];
#pragma unroll
    for (int np = 0; np < 2; np++) {
        int row = wid * 32 + np * 16 + (q >> 1) * 8 + rr;
        bbyte[np] = (uint32_t)(row * 128 + (q & 1) * 16);
    }

    float acc[2][4][4];
#pragma unroll
    for (int mt = 0; mt < 2; mt++)
#pragma unroll
        for (int nt = 0; nt < 4; nt++)
#pragma unroll
            for (int i = 0; i < 4; i++) acc[mt][nt][i] = 0.0f;

    // prologue: W2 stages 0,1
#pragma unroll
    for (int pk = 0; pk < 2; pk++) {
#pragma unroll
        for (int p = 0; p < 2; p++)
            CP_ASYNC16(w2smem + pk * PB_W2STAGE + p * PB_W2TILE + w_sdst,
                       &g_W2s[p][0] + w_goff + pk * PB_BK);
        CP_COMMIT();
    }
    uint32_t mcur[2];
#pragma unroll
    for (int i = 0; i < 2; i++) mcur[i] = mrow[i][0];

    for (int kc = 0; kc < PB_NCH; kc++) {
        __syncthreads();   // all warps done reading spkbuf[kc&1] (chunk kc-2)

        // expand masks -> spk bf16 tile
        char* sb = smem + (kc & 1) * PB_SPKBUF;
#pragma unroll
        for (int i = 0; i < 2; i++) {
            uint32_t W = mcur[i];
#pragma unroll
            for (int g = 0; g < 4; g++) {
                uint4 u;
                u.x = expand2((W >> (g * 8 + 0)) & 3u);
                u.y = expand2((W >> (g * 8 + 2)) & 3u);
                u.z = expand2((W >> (g * 8 + 4)) & 3u);
                u.w = expand2((W >> (g * 8 + 6)) & 3u);
                *(uint4*)(sb + SWZ128(ebase[i] + g * 16)) = u;
            }
        }
        CP_WAIT1();
        __syncthreads();   // expansion + W2 stage visible

        const uint32_t spkb = smem_base + (kc & 1) * PB_SPKBUF;
        const uint32_t w2b  = w2smem + (kc & 1) * PB_W2STAGE;
#pragma unroll
        for (int kk = 0; kk < 4; kk++) {
            uint32_t bf[4][2];
#pragma unroll
            for (int np = 0; np < 2; np++)
                ldsm_x4(bf[np * 2][0], bf[np * 2][1], bf[np * 2 + 1][0], bf[np * 2 + 1][1],
                        spkb + SWZ128(bbyte[np] + kk * 32));
#pragma unroll
            for (int p = 0; p < 2; p++) {
                uint32_t af[2][4];
#pragma unroll
                for (int mt = 0; mt < 2; mt++)
                    ldsm_x4(af[mt][0], af[mt][1], af[mt][2], af[mt][3],
                            w2b + p * PB_W2TILE + SWZ128(abyte[mt] + kk * 32));
#pragma unroll
                for (int mt = 0; mt < 2; mt++)
#pragma unroll
                    for (int nt = 0; nt < 4; nt++)
                        mma16816_bf16(acc[mt][nt], af[mt], bf[nt]);
            }
        }

        if (kc + 2 < PB_NCH) {
#pragma unroll
            for (int p = 0; p < 2; p++)
                CP_ASYNC16(w2smem + (kc & 1) * PB_W2STAGE + p * PB_W2TILE + w_sdst,
                           &g_W2s[p][0] + w_goff + (kc + 2) * PB_BK);
        }
        CP_COMMIT();
        if (kc + 1 < PB_NCH) {
#pragma unroll
            for (int i = 0; i < 2; i++) mcur[i] = mrow[i][(kc + 1) * 2];
        }
    }

#pragma unroll
    for (int mt = 0; mt < 2; mt++) {
#pragma unroll
        for (int nt = 0; nt < 4; nt++) {
            int o  = mt * 16 + (lane >> 2);
            int n  = wid * 32 + nt * 8 + (lane & 3) * 2;
            size_t gm = (size_t)(m0 + n);
            g_d2[gm * 32 + o]           = acc[mt][nt][0];
            g_d2[(gm + 1) * 32 + o]     = acc[mt][nt][1];
            g_d2[gm * 32 + o + 8]       = acc[mt][nt][2];
            g_d2[(gm + 1) * 32 + o + 8] = acc[mt][nt][3];
        }
    }
}

// ---------------------------------------------------------------------------
// Kernel 2c: readout EMA + softmax accumulate (max-free; |mem2|<<88 so safe).
// ---------------------------------------------------------------------------
__global__ __launch_bounds__(256) void readout_kernel(
    const float* __restrict__ tau2,
    const float* __restrict__ b2,
    float* __restrict__ out)
{
    const int warp = threadIdx.x >> 5;
    const int lane = threadIdx.x & 31;
    const int b = blockIdx.x * 8 + warp;

    float a2 = 0.0f, oma2 = 0.0f, bb = 0.0f, mem2 = 0.0f, accv = 0.0f;
    if (lane < O_) {
        a2 = 1.0f / (1.0f + expf(-tau2[lane]));
        oma2 = 1.0f - a2;
        bb = b2[lane];
    }

    const float* dp = g_d2 + (size_t)b * T_ * 32;
    float v = dp[lane];
    for (int t = 0; t < T_; t++) {
        float vn = (t + 1 < T_) ? dp[(size_t)(t + 1) * 32 + lane] : 0.0f;
        if (lane < O_) mem2 = mem2 * a2 + oma2 * (v + bb);
        float e = (lane < O_) ? expf(mem2) : 0.0f;
        float s = e;
#pragma unroll
        for (int off = 16; off > 0; off >>= 1)
            s += __shfl_xor_sync(0xffffffffu, s, off);
        if (t > 10 && lane < O_) accv += e / s;
        v = vn;
    }
    if (lane < O_) out[b * O_ + lane] = accv;
}

// ---------------------------------------------------------------------------
extern "C" void kernel_launch(void* const* d_in, const int* in_sizes, int n_in,
                              void* d_out, int out_size)
{
    const float* input = (const float*)d_in[0];  // [B,T,D]
    const float* W1    = (const float*)d_in[1];  // [H,D]
    const float* b1    = (const float*)d_in[2];  // [H]
    const float* tau1  = (const float*)d_in[3];  // [H]
    const float* W2    = (const float*)d_in[4];  // [O,H]
    const float* b2    = (const float*)d_in[5];  // [O]
    const float* tau2  = (const float*)d_in[6];  // [O]
    float* out = (float*)d_out;                  // [B,O]

    cudaFuncSetAttribute(gemm_hmma_kernel,
                         cudaFuncAttributeMaxDynamicSharedMemorySize, SMEM_TOTAL);
    cudaFuncSetAttribute(d2_gemm_kernel,
                         cudaFuncAttributeMaxDynamicSharedMemorySize, PB_SMEM);

    __half *ah, *al, *wh, *wl;
    float *d1p;
    cudaGetSymbolAddress((void**)&ah,  g_Ah);
    cudaGetSymbolAddress((void**)&al,  g_Al);
    cudaGetSymbolAddress((void**)&wh,  g_Wh);
    cudaGetSymbolAddress((void**)&wl,  g_Wl);
    cudaGetSymbolAddress((void**)&d1p, g_d1);

    {
        long long ng = (long long)M_ * (KP_ / 4);
        int blocks = (int)((ng + 255) / 256);
        split2_kernel<<<blocks, 256>>>(input, M_, A_SCALE, ah, al);
    }
    {
        long long ng = (long long)H_ * (KP_ / 4);
        int blocks = (int)((ng + 255) / 256);
        split2_kernel<<<blocks, 256>>>(W1, H_, W_SCALE, wh, wl);
    }
    split_w2_kernel<<<(32 * PB_K + 255) / 256, 256>>>(W2);

    dim3 ggrid(H_ / BN, M_ / BM);  // (16, 500)
    gemm_hmma_kernel<<<ggrid, 256, SMEM_TOTAL>>>(b1);

    lif1_kernel<<<2 * B_, 128>>>(d1p, tau1);
    d2_gemm_kernel<<<M_ / PB_ROWS, 256, PB_SMEM>>>();   // 250 CTAs
    readout_kernel<<<B_ / 8, 256>>>(tau2, b2, out);
}